// round 1
// baseline (speedup 1.0000x reference)
#include <cuda_runtime.h>
#include <math.h>

#define HDIM 256
#define NHEADS 8
#define DH 32
#define NMAX 4096

// ---------------- scratch (static __device__ arrays: no allocations) -------
__device__ __align__(16) float g_Q   [NMAX * HDIM];
__device__ __align__(16) float g_K   [NMAX * HDIM];
__device__ __align__(16) float g_V   [NMAX * HDIM];
__device__ __align__(16) float g_attH[NMAX * HDIM];
__device__ __align__(16) float g_att [NMAX * HDIM];
__device__ __align__(16) float g_Atop[NMAX * HDIM];
__device__ __align__(16) float g_Abot[NMAX * HDIM];
__device__ __align__(16) float g_Hsum[NMAX * HDIM];
__device__ __align__(16) float g_msg [NMAX * HDIM];
__device__ __align__(16) float g_T1  [NMAX * HDIM];
__device__ __align__(16) float g_deg [NMAX];

// ---------------- SGEMM: C = act(A[M,K] @ W[K,N] + bias (+ Dadd)) ----------
// BM=BN=64, BK=16, 256 threads, 4x4 micro-tile. A tile stored transposed in
// smem so both operand fetches are float4 LDS.
template<bool RELU, bool BIAS, bool ADD, bool DEGB>
__global__ void gemm_k(const float* __restrict__ A, const float* __restrict__ W,
                       const float* __restrict__ bias, const float* __restrict__ Dadd,
                       const float* __restrict__ deg, float* __restrict__ C,
                       int M, int K, int N)
{
    __shared__ float As[16][68];   // [k][m], padded
    __shared__ float Bs[16][64];   // [k][n]

    const int t  = threadIdx.x;          // 0..255
    const int bm = blockIdx.y * 64;
    const int bn = blockIdx.x * 64;
    const int tr = t >> 4;               // 0..15 (row group)
    const int tc = t & 15;               // 0..15 (col group)

    // load indices
    const int ar = t >> 2;               // 0..63
    const int ac = (t & 3) << 2;         // 0,4,8,12
    const int br = t >> 4;               // 0..15
    const int bc = (t & 15) << 2;        // 0..60

    float acc[4][4];
    #pragma unroll
    for (int i = 0; i < 4; i++)
        #pragma unroll
        for (int j = 0; j < 4; j++) acc[i][j] = 0.f;

    for (int k0 = 0; k0 < K; k0 += 16) {
        float4 av = *(const float4*)&A[(size_t)(bm + ar) * K + k0 + ac];
        As[ac + 0][ar] = av.x;
        As[ac + 1][ar] = av.y;
        As[ac + 2][ar] = av.z;
        As[ac + 3][ar] = av.w;
        *(float4*)&Bs[br][bc] = *(const float4*)&W[(size_t)(k0 + br) * N + bn + bc];
        __syncthreads();

        #pragma unroll
        for (int k = 0; k < 16; k++) {
            float4 a4 = *(float4*)&As[k][tr << 2];
            float4 b4 = *(float4*)&Bs[k][tc << 2];
            float aa[4] = {a4.x, a4.y, a4.z, a4.w};
            float bb[4] = {b4.x, b4.y, b4.z, b4.w};
            #pragma unroll
            for (int i = 0; i < 4; i++)
                #pragma unroll
                for (int j = 0; j < 4; j++)
                    acc[i][j] = fmaf(aa[i], bb[j], acc[i][j]);
        }
        __syncthreads();
    }

    #pragma unroll
    for (int i = 0; i < 4; i++) {
        int row = bm + (tr << 2) + i;
        float dscale = DEGB ? deg[row] : 1.f;
        #pragma unroll
        for (int j = 0; j < 4; j++) {
            int col = bn + (tc << 2) + j;
            float v = acc[i][j];
            if (ADD)  v += Dadd[(size_t)row * N + col];
            if (BIAS) v += (DEGB ? dscale * bias[col] : bias[col]);
            if (RELU) v = fmaxf(v, 0.f);
            C[(size_t)row * N + col] = v;
        }
    }
}

// ---------------- flash attention (fp32, dh=32, thread-per-query) ----------
// Block: 128 threads = 128 queries of one head. Tiles of 128 keys in smem.
// Online softmax with running max; rescale branch fires ~ln(4096) times.
__global__ void flash_k(const float* __restrict__ Q, const float* __restrict__ Km,
                        const float* __restrict__ Vm, float* __restrict__ O, int N)
{
    __shared__ float Ks[128][DH];
    __shared__ float Vs[128][DH];

    const int h = blockIdx.y;
    const int q = blockIdx.x * 128 + threadIdx.x;
    const float sc = 1.44269504088896f / sqrtf((float)DH);  // log2e / sqrt(dh)

    float qr[DH];
    #pragma unroll
    for (int i = 0; i < DH; i += 4) {
        float4 v = *(const float4*)&Q[(size_t)q * HDIM + h * DH + i];
        qr[i + 0] = v.x * sc; qr[i + 1] = v.y * sc;
        qr[i + 2] = v.z * sc; qr[i + 3] = v.w * sc;
    }

    float m = -1e30f, l = 0.f;
    float o[DH];
    #pragma unroll
    for (int d = 0; d < DH; d++) o[d] = 0.f;

    for (int kb = 0; kb < N; kb += 128) {
        // cooperative, coalesced tile load: 128 rows x 8 float4
        for (int f = threadIdx.x; f < 128 * 8; f += 128) {
            int row = f >> 3, seg = (f & 7) << 2;
            size_t g = (size_t)(kb + row) * HDIM + h * DH + seg;
            *(float4*)&Ks[row][seg] = *(const float4*)&Km[g];
            *(float4*)&Vs[row][seg] = *(const float4*)&Vm[g];
        }
        __syncthreads();

        for (int j = 0; j < 128; j++) {
            float s = 0.f;
            #pragma unroll
            for (int d = 0; d < DH; d += 4) {
                float4 kv = *(float4*)&Ks[j][d];
                s = fmaf(qr[d + 0], kv.x, s);
                s = fmaf(qr[d + 1], kv.y, s);
                s = fmaf(qr[d + 2], kv.z, s);
                s = fmaf(qr[d + 3], kv.w, s);
            }
            if (s > m) {                         // rare: new running max
                float c = exp2f(m - s);
                m = s;
                l = l * c + 1.f;
                #pragma unroll
                for (int d = 0; d < DH; d += 4) {
                    float4 vv = *(float4*)&Vs[j][d];
                    o[d + 0] = fmaf(o[d + 0], c, vv.x);
                    o[d + 1] = fmaf(o[d + 1], c, vv.y);
                    o[d + 2] = fmaf(o[d + 2], c, vv.z);
                    o[d + 3] = fmaf(o[d + 3], c, vv.w);
                }
            } else {
                float p = exp2f(s - m);
                l += p;
                #pragma unroll
                for (int d = 0; d < DH; d += 4) {
                    float4 vv = *(float4*)&Vs[j][d];
                    o[d + 0] = fmaf(p, vv.x, o[d + 0]);
                    o[d + 1] = fmaf(p, vv.y, o[d + 1]);
                    o[d + 2] = fmaf(p, vv.z, o[d + 2]);
                    o[d + 3] = fmaf(p, vv.w, o[d + 3]);
                }
            }
        }
        __syncthreads();
    }

    float inv = 1.f / l;
    #pragma unroll
    for (int d = 0; d < DH; d += 4) {
        float4 r;
        r.x = o[d + 0] * inv; r.y = o[d + 1] * inv;
        r.z = o[d + 2] * inv; r.w = o[d + 3] * inv;
        *(float4*)&O[(size_t)q * HDIM + h * DH + d] = r;
    }
}

// ---------------- edge kernel: Hsum[dst] += relu(Atop[src] + Abot[dst]) ----
// One warp per edge; 2 float4 per lane covers 256 floats. Gathers hit L2
// (Atop/Abot are 4 MB each). Scalar atomicAdd lowers to REDG.
__global__ void edge_k(const float* __restrict__ At, const float* __restrict__ Ab,
                       const int* __restrict__ edges, float* __restrict__ Hsum,
                       float* __restrict__ deg, int E)
{
    const int lane   = threadIdx.x & 31;
    const int gw     = (blockIdx.x * blockDim.x + threadIdx.x) >> 5;
    const int nwarps = (gridDim.x * blockDim.x) >> 5;

    for (int e = gw; e < E; e += nwarps) {
        int src = edges[2 * e + 0];
        int dst = edges[2 * e + 1];
        const float4* ps = (const float4*)(At + (size_t)src * HDIM);
        const float4* pd = (const float4*)(Ab + (size_t)dst * HDIM);
        float* po = Hsum + (size_t)dst * HDIM;
        #pragma unroll
        for (int i = 0; i < 2; i++) {
            int idx = lane + 32 * i;          // float4 index 0..63
            float4 a = ps[idx], b = pd[idx];
            float4 r;
            r.x = fmaxf(a.x + b.x, 0.f);
            r.y = fmaxf(a.y + b.y, 0.f);
            r.z = fmaxf(a.z + b.z, 0.f);
            r.w = fmaxf(a.w + b.w, 0.f);
            atomicAdd(po + idx * 4 + 0, r.x);
            atomicAdd(po + idx * 4 + 1, r.y);
            atomicAdd(po + idx * 4 + 2, r.z);
            atomicAdd(po + idx * 4 + 3, r.w);
        }
        if (lane == 0) atomicAdd(deg + dst, 1.f);
    }
}

// ---------------- launch ---------------------------------------------------
extern "C" void kernel_launch(void* const* d_in, const int* in_sizes, int n_in,
                              void* d_out, int out_size)
{
    const float* x    = (const float*)d_in[0];
    const int*   edges= (const int*)  d_in[1];
    const float* Wq   = (const float*)d_in[2];
    const float* Wk   = (const float*)d_in[3];
    const float* Wv   = (const float*)d_in[4];
    const float* bq   = (const float*)d_in[5];
    const float* bk   = (const float*)d_in[6];
    const float* bv   = (const float*)d_in[7];
    const float* Wo   = (const float*)d_in[8];
    const float* bo   = (const float*)d_in[9];
    const float* Wm1  = (const float*)d_in[10];
    const float* bm1  = (const float*)d_in[11];
    const float* Wm2  = (const float*)d_in[12];
    const float* bm2  = (const float*)d_in[13];
    const float* Wu1  = (const float*)d_in[14];
    const float* bu1  = (const float*)d_in[15];
    const float* Wu2  = (const float*)d_in[16];
    const float* bu2  = (const float*)d_in[17];
    float* out = (float*)d_out;

    const int N = in_sizes[0] / HDIM;   // 4096
    const int E = in_sizes[1] / 2;      // 131072

    float *Q, *K, *V, *attH, *att, *Atop, *Abot, *Hsum, *msg, *T1, *deg;
    cudaGetSymbolAddress((void**)&Q,    g_Q);
    cudaGetSymbolAddress((void**)&K,    g_K);
    cudaGetSymbolAddress((void**)&V,    g_V);
    cudaGetSymbolAddress((void**)&attH, g_attH);
    cudaGetSymbolAddress((void**)&att,  g_att);
    cudaGetSymbolAddress((void**)&Atop, g_Atop);
    cudaGetSymbolAddress((void**)&Abot, g_Abot);
    cudaGetSymbolAddress((void**)&Hsum, g_Hsum);
    cudaGetSymbolAddress((void**)&msg,  g_msg);
    cudaGetSymbolAddress((void**)&T1,   g_T1);
    cudaGetSymbolAddress((void**)&deg,  g_deg);

    dim3 gB(256);
    dim3 gG(HDIM / 64, N / 64);         // (4, 64)

    cudaMemsetAsync(Hsum, 0, (size_t)N * HDIM * sizeof(float));
    cudaMemsetAsync(deg,  0, (size_t)N * sizeof(float));

    // QKV projections
    gemm_k<false, true, false, false><<<gG, gB>>>(x, Wq, bq, nullptr, nullptr, Q, N, HDIM, HDIM);
    gemm_k<false, true, false, false><<<gG, gB>>>(x, Wk, bk, nullptr, nullptr, K, N, HDIM, HDIM);
    gemm_k<false, true, false, false><<<gG, gB>>>(x, Wv, bv, nullptr, nullptr, V, N, HDIM, HDIM);

    // attention
    flash_k<<<dim3(N / 128, NHEADS), 128>>>(Q, K, V, attH, N);

    // output projection
    gemm_k<false, true, false, false><<<gG, gB>>>(attH, Wo, bo, nullptr, nullptr, att, N, HDIM, HDIM);

    // edge MLP layer-1 factorization: Atop = att@Wm1[:256] + bm1 ; Abot = att@Wm1[256:]
    gemm_k<false, true,  false, false><<<gG, gB>>>(att, Wm1,             bm1, nullptr, nullptr, Atop, N, HDIM, HDIM);
    gemm_k<false, false, false, false><<<gG, gB>>>(att, Wm1 + HDIM*HDIM, nullptr, nullptr, nullptr, Abot, N, HDIM, HDIM);

    // per-edge relu + segment-sum of hidden
    edge_k<<<512, 256>>>(Atop, Abot, edges, Hsum, deg, E);

    // messages = Hsum @ Wm2 + deg * bm2   (Wm2 pushed through segment_sum)
    gemm_k<false, true, false, true><<<gG, gB>>>(Hsum, Wm2, bm2, nullptr, deg, msg, N, HDIM, HDIM);

    // update MLP: T1 = att@Wu1[:256] + bu1 ; T1 = relu(msg@Wu1[256:] + T1)
    gemm_k<false, true, false, false><<<gG, gB>>>(att, Wu1,             bu1, nullptr, nullptr, T1, N, HDIM, HDIM);
    gemm_k<true,  false, true, false><<<gG, gB>>>(msg, Wu1 + HDIM*HDIM, nullptr, T1, nullptr, T1, N, HDIM, HDIM);

    // output
    gemm_k<false, true, false, false><<<gG, gB>>>(T1, Wu2, bu2, nullptr, nullptr, out, N, HDIM, HDIM);
}

// round 2
// speedup vs baseline: 1.2580x; 1.2580x over previous
#include <cuda_runtime.h>
#include <math.h>

#define HDIM 256
#define NHEADS 8
#define DH 32
#define NMAX 4096

// ---------------- scratch (static __device__ arrays: no allocations) -------
__device__ __align__(16) float g_Q   [NMAX * HDIM];
__device__ __align__(16) float g_K   [NMAX * HDIM];
__device__ __align__(16) float g_V   [NMAX * HDIM];
__device__ __align__(16) float g_attH[NMAX * HDIM];
__device__ __align__(16) float g_att [NMAX * HDIM];
__device__ __align__(16) float g_Atop[NMAX * HDIM];
__device__ __align__(16) float g_Abot[NMAX * HDIM];
__device__ __align__(16) float g_Hsum[NMAX * HDIM];
__device__ __align__(16) float g_msg [NMAX * HDIM];
__device__ __align__(16) float g_T1  [NMAX * HDIM];
__device__ __align__(16) float g_deg [NMAX];

// ---------------- SGEMM: C = act(A[M,K] @ W[K,N] + bias (+ Dadd)) ----------
template<bool RELU, bool BIAS, bool ADD, bool DEGB>
__global__ void gemm_k(const float* __restrict__ A, const float* __restrict__ W,
                       const float* __restrict__ bias, const float* __restrict__ Dadd,
                       const float* __restrict__ deg, float* __restrict__ C,
                       int M, int K, int N)
{
    __shared__ float As[16][68];   // [k][m], padded
    __shared__ float Bs[16][64];   // [k][n]

    const int t  = threadIdx.x;          // 0..255
    const int bm = blockIdx.y * 64;
    const int bn = blockIdx.x * 64;
    const int tr = t >> 4;               // 0..15 (row group)
    const int tc = t & 15;               // 0..15 (col group)

    const int ar = t >> 2;               // 0..63
    const int ac = (t & 3) << 2;         // 0,4,8,12
    const int br = t >> 4;               // 0..15
    const int bc = (t & 15) << 2;        // 0..60

    float acc[4][4];
    #pragma unroll
    for (int i = 0; i < 4; i++)
        #pragma unroll
        for (int j = 0; j < 4; j++) acc[i][j] = 0.f;

    for (int k0 = 0; k0 < K; k0 += 16) {
        float4 av = *(const float4*)&A[(size_t)(bm + ar) * K + k0 + ac];
        As[ac + 0][ar] = av.x;
        As[ac + 1][ar] = av.y;
        As[ac + 2][ar] = av.z;
        As[ac + 3][ar] = av.w;
        *(float4*)&Bs[br][bc] = *(const float4*)&W[(size_t)(k0 + br) * N + bn + bc];
        __syncthreads();

        #pragma unroll
        for (int k = 0; k < 16; k++) {
            float4 a4 = *(float4*)&As[k][tr << 2];
            float4 b4 = *(float4*)&Bs[k][tc << 2];
            float aa[4] = {a4.x, a4.y, a4.z, a4.w};
            float bb[4] = {b4.x, b4.y, b4.z, b4.w};
            #pragma unroll
            for (int i = 0; i < 4; i++)
                #pragma unroll
                for (int j = 0; j < 4; j++)
                    acc[i][j] = fmaf(aa[i], bb[j], acc[i][j]);
        }
        __syncthreads();
    }

    #pragma unroll
    for (int i = 0; i < 4; i++) {
        int row = bm + (tr << 2) + i;
        float dscale = DEGB ? deg[row] : 1.f;
        #pragma unroll
        for (int j = 0; j < 4; j++) {
            int col = bn + (tc << 2) + j;
            float v = acc[i][j];
            if (ADD)  v += Dadd[(size_t)row * N + col];
            if (BIAS) v += (DEGB ? dscale * bias[col] : bias[col]);
            if (RELU) v = fmaxf(v, 0.f);
            C[(size_t)row * N + col] = v;
        }
    }
}

// ---------------- GEMM-tiled flash attention (fp32, dh=32) -----------------
// Block: 256 threads, 64 queries of one head, key tiles of 64.
// S = Q@K^T via 4x4 register micro-tile (16 independent FFMA accumulators),
// online softmax with 16-lane butterfly reductions (per-row state replicated
// across the 16 tc threads), P staged transposed in smem, PV GEMM with 4x2
// micro-tile (4 query rows x 2 dh dims per thread).
__global__ void __launch_bounds__(256) flash_k(
    const float* __restrict__ Qm, const float* __restrict__ Km,
    const float* __restrict__ Vm, float* __restrict__ O, int N)
{
    __shared__ float Qs[DH][68];   // Q^T for this block's 64 queries
    __shared__ float Ks[DH][68];   // K^T tile
    __shared__ float Vs[64][36];   // V tile [key][d]
    __shared__ float Pt[64][68];   // P^T [key][query]

    const int t  = threadIdx.x;
    const int h  = blockIdx.y;
    const int q0 = blockIdx.x * 64;
    const int tr = t >> 4;               // query group 0..15
    const int tc = t & 15;               // key/dh group 0..15
    const float sc = 1.44269504088896f / sqrtf((float)DH);

    // load Q^T once (coalesced: consecutive threads -> consecutive d)
    for (int i = t; i < 64 * DH; i += 256) {
        int d = i & 31, m = i >> 5;
        Qs[d][m] = Qm[(size_t)(q0 + m) * HDIM + h * DH + d] * sc;
    }

    float mi[4], li[4], o[4][2];
    #pragma unroll
    for (int i = 0; i < 4; i++) {
        mi[i] = -1e30f; li[i] = 0.f; o[i][0] = 0.f; o[i][1] = 0.f;
    }

    for (int kb = 0; kb < N; kb += 64) {
        __syncthreads();   // prev PV done before overwriting Ks/Vs
        for (int i = t; i < 64 * DH; i += 256) {
            int d = i & 31, n = i >> 5;
            Ks[d][n] = Km[(size_t)(kb + n) * HDIM + h * DH + d];
        }
        for (int i = t; i < 64 * DH; i += 256) {
            int d = i & 31, j = i >> 5;
            Vs[j][d] = Vm[(size_t)(kb + j) * HDIM + h * DH + d];
        }
        __syncthreads();

        // S tile: acc[i][j] = q(tr*4+i) . k(tc*4+j)
        float acc[4][4];
        #pragma unroll
        for (int i = 0; i < 4; i++)
            #pragma unroll
            for (int j = 0; j < 4; j++) acc[i][j] = 0.f;

        #pragma unroll
        for (int k = 0; k < DH; k++) {
            float4 a4 = *(float4*)&Qs[k][tr << 2];
            float4 b4 = *(float4*)&Ks[k][tc << 2];
            float aa[4] = {a4.x, a4.y, a4.z, a4.w};
            float bb[4] = {b4.x, b4.y, b4.z, b4.w};
            #pragma unroll
            for (int i = 0; i < 4; i++)
                #pragma unroll
                for (int j = 0; j < 4; j++)
                    acc[i][j] = fmaf(aa[i], bb[j], acc[i][j]);
        }

        // online softmax per query row (state replicated across 16 tc lanes)
        #pragma unroll
        for (int i = 0; i < 4; i++) {
            float rm = fmaxf(fmaxf(acc[i][0], acc[i][1]),
                             fmaxf(acc[i][2], acc[i][3]));
            #pragma unroll
            for (int off = 8; off > 0; off >>= 1)
                rm = fmaxf(rm, __shfl_xor_sync(0xffffffffu, rm, off));
            float mn = fmaxf(mi[i], rm);
            float c  = exp2f(mi[i] - mn);
            float rs = 0.f;
            #pragma unroll
            for (int j = 0; j < 4; j++) {
                acc[i][j] = exp2f(acc[i][j] - mn);
                rs += acc[i][j];
            }
            #pragma unroll
            for (int off = 8; off > 0; off >>= 1)
                rs += __shfl_xor_sync(0xffffffffu, rs, off);
            li[i] = li[i] * c + rs;
            mi[i] = mn;
            o[i][0] *= c;
            o[i][1] *= c;
        }

        // stage P transposed: Pt[key][query]
        #pragma unroll
        for (int jo = 0; jo < 4; jo++) {
            *(float4*)&Pt[(tc << 2) + jo][tr << 2] =
                make_float4(acc[0][jo], acc[1][jo], acc[2][jo], acc[3][jo]);
        }
        __syncthreads();

        // PV: o[i][d] += sum_j P[m][j] * V[j][d], d slice = tc*2..+1
        #pragma unroll 4
        for (int j = 0; j < 64; j++) {
            float4 p4 = *(float4*)&Pt[j][tr << 2];
            float2 v2 = *(float2*)&Vs[j][tc << 1];
            o[0][0] = fmaf(p4.x, v2.x, o[0][0]);
            o[0][1] = fmaf(p4.x, v2.y, o[0][1]);
            o[1][0] = fmaf(p4.y, v2.x, o[1][0]);
            o[1][1] = fmaf(p4.y, v2.y, o[1][1]);
            o[2][0] = fmaf(p4.z, v2.x, o[2][0]);
            o[2][1] = fmaf(p4.z, v2.y, o[2][1]);
            o[3][0] = fmaf(p4.w, v2.x, o[3][0]);
            o[3][1] = fmaf(p4.w, v2.y, o[3][1]);
        }
    }

    #pragma unroll
    for (int i = 0; i < 4; i++) {
        float inv = 1.f / li[i];
        size_t g = (size_t)(q0 + (tr << 2) + i) * HDIM + h * DH + (tc << 1);
        *(float2*)&O[g] = make_float2(o[i][0] * inv, o[i][1] * inv);
    }
}

// ---------------- edge kernel: Hsum[dst] += relu(Atop[src] + Abot[dst]) ----
// One warp per edge; vector red.global.add.v4.f32 quarters the atomic count.
__global__ void edge_k(const float* __restrict__ At, const float* __restrict__ Ab,
                       const int* __restrict__ edges, float* __restrict__ Hsum,
                       float* __restrict__ deg, int E)
{
    const int lane   = threadIdx.x & 31;
    const int gw     = (blockIdx.x * blockDim.x + threadIdx.x) >> 5;
    const int nwarps = (gridDim.x * blockDim.x) >> 5;

    for (int e = gw; e < E; e += nwarps) {
        int src = edges[2 * e + 0];
        int dst = edges[2 * e + 1];
        const float4* ps = (const float4*)(At + (size_t)src * HDIM);
        const float4* pd = (const float4*)(Ab + (size_t)dst * HDIM);
        float* po = Hsum + (size_t)dst * HDIM;
        #pragma unroll
        for (int i = 0; i < 2; i++) {
            int idx = lane + 32 * i;          // float4 index 0..63
            float4 a = ps[idx], b = pd[idx];
            float4 r;
            r.x = fmaxf(a.x + b.x, 0.f);
            r.y = fmaxf(a.y + b.y, 0.f);
            r.z = fmaxf(a.z + b.z, 0.f);
            r.w = fmaxf(a.w + b.w, 0.f);
            asm volatile("red.global.add.v4.f32 [%0], {%1, %2, %3, %4};"
                         :: "l"(po + idx * 4), "f"(r.x), "f"(r.y), "f"(r.z), "f"(r.w)
                         : "memory");
        }
        if (lane == 0) atomicAdd(deg + dst, 1.f);
    }
}

// ---------------- launch ---------------------------------------------------
extern "C" void kernel_launch(void* const* d_in, const int* in_sizes, int n_in,
                              void* d_out, int out_size)
{
    const float* x    = (const float*)d_in[0];
    const int*   edges= (const int*)  d_in[1];
    const float* Wq   = (const float*)d_in[2];
    const float* Wk   = (const float*)d_in[3];
    const float* Wv   = (const float*)d_in[4];
    const float* bq   = (const float*)d_in[5];
    const float* bk   = (const float*)d_in[6];
    const float* bv   = (const float*)d_in[7];
    const float* Wo   = (const float*)d_in[8];
    const float* bo   = (const float*)d_in[9];
    const float* Wm1  = (const float*)d_in[10];
    const float* bm1  = (const float*)d_in[11];
    const float* Wm2  = (const float*)d_in[12];
    const float* bm2  = (const float*)d_in[13];
    const float* Wu1  = (const float*)d_in[14];
    const float* bu1  = (const float*)d_in[15];
    const float* Wu2  = (const float*)d_in[16];
    const float* bu2  = (const float*)d_in[17];
    float* out = (float*)d_out;

    const int N = in_sizes[0] / HDIM;   // 4096
    const int E = in_sizes[1] / 2;      // 131072

    float *Q, *K, *V, *attH, *att, *Atop, *Abot, *Hsum, *msg, *T1, *deg;
    cudaGetSymbolAddress((void**)&Q,    g_Q);
    cudaGetSymbolAddress((void**)&K,    g_K);
    cudaGetSymbolAddress((void**)&V,    g_V);
    cudaGetSymbolAddress((void**)&attH, g_attH);
    cudaGetSymbolAddress((void**)&att,  g_att);
    cudaGetSymbolAddress((void**)&Atop, g_Atop);
    cudaGetSymbolAddress((void**)&Abot, g_Abot);
    cudaGetSymbolAddress((void**)&Hsum, g_Hsum);
    cudaGetSymbolAddress((void**)&msg,  g_msg);
    cudaGetSymbolAddress((void**)&T1,   g_T1);
    cudaGetSymbolAddress((void**)&deg,  g_deg);

    dim3 gB(256);
    dim3 gG(HDIM / 64, N / 64);         // (4, 64)

    cudaMemsetAsync(Hsum, 0, (size_t)N * HDIM * sizeof(float));
    cudaMemsetAsync(deg,  0, (size_t)N * sizeof(float));

    // QKV projections
    gemm_k<false, true, false, false><<<gG, gB>>>(x, Wq, bq, nullptr, nullptr, Q, N, HDIM, HDIM);
    gemm_k<false, true, false, false><<<gG, gB>>>(x, Wk, bk, nullptr, nullptr, K, N, HDIM, HDIM);
    gemm_k<false, true, false, false><<<gG, gB>>>(x, Wv, bv, nullptr, nullptr, V, N, HDIM, HDIM);

    // attention
    flash_k<<<dim3(N / 64, NHEADS), 256>>>(Q, K, V, attH, N);

    // output projection
    gemm_k<false, true, false, false><<<gG, gB>>>(attH, Wo, bo, nullptr, nullptr, att, N, HDIM, HDIM);

    // edge MLP layer-1 factorization
    gemm_k<false, true,  false, false><<<gG, gB>>>(att, Wm1,             bm1, nullptr, nullptr, Atop, N, HDIM, HDIM);
    gemm_k<false, false, false, false><<<gG, gB>>>(att, Wm1 + HDIM*HDIM, nullptr, nullptr, nullptr, Abot, N, HDIM, HDIM);

    // per-edge relu + segment-sum of hidden
    edge_k<<<512, 256>>>(Atop, Abot, edges, Hsum, deg, E);

    // messages = Hsum @ Wm2 + deg * bm2
    gemm_k<false, true, false, true><<<gG, gB>>>(Hsum, Wm2, bm2, nullptr, deg, msg, N, HDIM, HDIM);

    // update MLP
    gemm_k<false, true, false, false><<<gG, gB>>>(att, Wu1,             bu1, nullptr, nullptr, T1, N, HDIM, HDIM);
    gemm_k<true,  false, true, false><<<gG, gB>>>(msg, Wu1 + HDIM*HDIM, nullptr, T1, nullptr, T1, N, HDIM, HDIM);

    // output
    gemm_k<false, true, false, false><<<gG, gB>>>(T1, Wu2, bu2, nullptr, nullptr, out, N, HDIM, HDIM);
}

// round 3
// speedup vs baseline: 1.7022x; 1.3531x over previous
#include <cuda_runtime.h>
#include <math.h>
#include <stdint.h>

#define HDIM 256
#define NHEADS 8
#define DH 32
#define NMAX 4096

// ---------------- scratch (static __device__ arrays: no allocations) -------
__device__ __align__(16) float g_Q   [NMAX * HDIM];
__device__ __align__(16) float g_K   [NMAX * HDIM];
__device__ __align__(16) float g_V   [NMAX * HDIM];
__device__ __align__(16) float g_attH[NMAX * HDIM];
__device__ __align__(16) float g_att [NMAX * HDIM];
__device__ __align__(16) float g_Atop[NMAX * HDIM];
__device__ __align__(16) float g_Abot[NMAX * HDIM];
__device__ __align__(16) float g_Hsum[NMAX * HDIM];
__device__ __align__(16) float g_msg [NMAX * HDIM];
__device__ __align__(16) float g_T1  [NMAX * HDIM];
__device__ __align__(16) float g_deg [NMAX];

// ---------------- SGEMM: C = act(A[M,K] @ W[K,N] + bias (+ Dadd)) ----------
template<bool RELU, bool BIAS, bool ADD, bool DEGB>
__global__ void gemm_k(const float* __restrict__ A, const float* __restrict__ W,
                       const float* __restrict__ bias, const float* __restrict__ Dadd,
                       const float* __restrict__ deg, float* __restrict__ C,
                       int M, int K, int N)
{
    __shared__ float As[16][68];   // [k][m], padded
    __shared__ float Bs[16][64];   // [k][n]

    const int t  = threadIdx.x;          // 0..255
    const int bm = blockIdx.y * 64;
    const int bn = blockIdx.x * 64;
    const int tr = t >> 4;               // 0..15 (row group)
    const int tc = t & 15;               // 0..15 (col group)

    const int ar = t >> 2;               // 0..63
    const int ac = (t & 3) << 2;         // 0,4,8,12
    const int br = t >> 4;               // 0..15
    const int bc = (t & 15) << 2;        // 0..60

    float acc[4][4];
    #pragma unroll
    for (int i = 0; i < 4; i++)
        #pragma unroll
        for (int j = 0; j < 4; j++) acc[i][j] = 0.f;

    for (int k0 = 0; k0 < K; k0 += 16) {
        float4 av = *(const float4*)&A[(size_t)(bm + ar) * K + k0 + ac];
        As[ac + 0][ar] = av.x;
        As[ac + 1][ar] = av.y;
        As[ac + 2][ar] = av.z;
        As[ac + 3][ar] = av.w;
        *(float4*)&Bs[br][bc] = *(const float4*)&W[(size_t)(k0 + br) * N + bn + bc];
        __syncthreads();

        #pragma unroll
        for (int k = 0; k < 16; k++) {
            float4 a4 = *(float4*)&As[k][tr << 2];
            float4 b4 = *(float4*)&Bs[k][tc << 2];
            float aa[4] = {a4.x, a4.y, a4.z, a4.w};
            float bb[4] = {b4.x, b4.y, b4.z, b4.w};
            #pragma unroll
            for (int i = 0; i < 4; i++)
                #pragma unroll
                for (int j = 0; j < 4; j++)
                    acc[i][j] = fmaf(aa[i], bb[j], acc[i][j]);
        }
        __syncthreads();
    }

    #pragma unroll
    for (int i = 0; i < 4; i++) {
        int row = bm + (tr << 2) + i;
        float dscale = DEGB ? deg[row] : 1.f;
        #pragma unroll
        for (int j = 0; j < 4; j++) {
            int col = bn + (tc << 2) + j;
            float v = acc[i][j];
            if (ADD)  v += Dadd[(size_t)row * N + col];
            if (BIAS) v += (DEGB ? dscale * bias[col] : bias[col]);
            if (RELU) v = fmaxf(v, 0.f);
            C[(size_t)row * N + col] = v;
        }
    }
}

// ---------------- tensor-core flash attention (3xTF32 mma.sync) -------------
// Block: 256 threads / 8 warps, 128 queries of one head. Warp owns 16 query
// rows. Key tiles of 64. S = Q@K^T and O += P@V via mma.sync.m16n8k8.tf32
// with the 3xTF32 hi/lo decomposition (fp32-level accuracy).
// P goes C-fragment -> A-fragment via register shuffles (no smem round trip).

__device__ __forceinline__ uint32_t f2tf(float x) {
    uint32_t r;
    asm("cvt.rna.tf32.f32 %0, %1;" : "=r"(r) : "f"(x));
    return r;
}
__device__ __forceinline__ void tfsplit(float x, uint32_t& hi, uint32_t& lo) {
    hi = f2tf(x);
    lo = f2tf(x - __uint_as_float(hi));
}
__device__ __forceinline__ void mma_tf32(float d[4], const uint32_t a[4],
                                         uint32_t b0, uint32_t b1) {
    asm volatile(
        "mma.sync.aligned.m16n8k8.row.col.f32.tf32.tf32.f32 "
        "{%0,%1,%2,%3}, {%4,%5,%6,%7}, {%8,%9}, {%0,%1,%2,%3};"
        : "+f"(d[0]), "+f"(d[1]), "+f"(d[2]), "+f"(d[3])
        : "r"(a[0]), "r"(a[1]), "r"(a[2]), "r"(a[3]), "r"(b0), "r"(b1));
}

#define KS_STR 36
#define VS_STR 40

__global__ void __launch_bounds__(256) flash_mma(
    const float* __restrict__ Qm, const float* __restrict__ Km,
    const float* __restrict__ Vm, float* __restrict__ O, int N)
{
    __shared__ float Ks[64 * KS_STR];   // K tile [key][d] (also Q staging rows 0-63)
    __shared__ float Vs[64 * VS_STR];   // V tile [key][d] (also Q staging rows 64-127)

    const int t    = threadIdx.x;
    const int w    = t >> 5;
    const int lane = t & 31;
    const int g    = lane >> 2;          // group id (row within fragment)
    const int tq   = lane & 3;           // thread in group
    const int h    = blockIdx.y;
    const int q0   = blockIdx.x * 128;
    const float sc = 1.44269504088896f / sqrtf((float)DH);

    // ---- stage Q tile (128 x 32) into Ks/Vs regions, coalesced ----
    for (int i = t; i < 128 * 8; i += 256) {
        int row = i >> 3, c = (i & 7) << 2;
        float4 qv = *(const float4*)&Qm[(size_t)(q0 + row) * HDIM + h * DH + c];
        float* dst = (row < 64) ? &Ks[row * KS_STR + c]
                                : &Vs[(row - 64) * VS_STR + c];
        *(float4*)dst = qv;
    }
    __syncthreads();

    // ---- extract Q fragments (hi/lo), scaled; kept in regs all kernel ----
    uint32_t qhi[4][4], qlo[4][4];
    {
        int r0 = w * 16 + g;
        int r1 = r0 + 8;
        const float* p0 = (r0 < 64) ? &Ks[r0 * KS_STR] : &Vs[(r0 - 64) * VS_STR];
        const float* p1 = (r1 < 64) ? &Ks[r1 * KS_STR] : &Vs[(r1 - 64) * VS_STR];
        #pragma unroll
        for (int kc = 0; kc < 4; kc++) {
            int c0 = kc * 8 + tq, c1 = c0 + 4;
            float a0 = p0[c0] * sc, a1 = p1[c0] * sc;
            float a2 = p0[c1] * sc, a3 = p1[c1] * sc;
            tfsplit(a0, qhi[kc][0], qlo[kc][0]);
            tfsplit(a1, qhi[kc][1], qlo[kc][1]);
            tfsplit(a2, qhi[kc][2], qlo[kc][2]);
            tfsplit(a3, qhi[kc][3], qlo[kc][3]);
        }
    }

    float oacc[4][4];                    // 4 dh-blocks x C-frag
    #pragma unroll
    for (int i = 0; i < 4; i++)
        #pragma unroll
        for (int j = 0; j < 4; j++) oacc[i][j] = 0.f;
    float mi[2] = {-1e30f, -1e30f};
    float li[2] = {0.f, 0.f};

    for (int kb = 0; kb < N; kb += 64) {
        __syncthreads();   // previous tile fully consumed (incl. Q staging)
        for (int i = t; i < 64 * 8; i += 256) {
            int n = i >> 3, c = (i & 7) << 2;
            size_t gidx = (size_t)(kb + n) * HDIM + h * DH + c;
            *(float4*)&Ks[n * KS_STR + c] = *(const float4*)&Km[gidx];
            *(float4*)&Vs[n * VS_STR + c] = *(const float4*)&Vm[gidx];
        }
        __syncthreads();

        // ---- S = Q @ K^T : 8 key-blocks of 8, 3xTF32 ----
        float sb[8][4];
        #pragma unroll
        for (int nb = 0; nb < 8; nb++)
            #pragma unroll
            for (int j = 0; j < 4; j++) sb[nb][j] = 0.f;

        #pragma unroll
        for (int kc = 0; kc < 4; kc++) {
            #pragma unroll
            for (int nb = 0; nb < 8; nb++) {
                float b0f = Ks[(nb * 8 + g) * KS_STR + kc * 8 + tq];
                float b1f = Ks[(nb * 8 + g) * KS_STR + kc * 8 + tq + 4];
                uint32_t b0h, b0l, b1h, b1l;
                tfsplit(b0f, b0h, b0l);
                tfsplit(b1f, b1h, b1l);
                mma_tf32(sb[nb], qhi[kc], b0h, b1h);
                mma_tf32(sb[nb], qlo[kc], b0h, b1h);
                mma_tf32(sb[nb], qhi[kc], b0l, b1l);
            }
        }

        // ---- online softmax on C fragments ----
        float cfac[2];
        #pragma unroll
        for (int hf = 0; hf < 2; hf++) {
            int e0 = hf * 2, e1 = hf * 2 + 1;
            float rm = -1e30f;
            #pragma unroll
            for (int nb = 0; nb < 8; nb++)
                rm = fmaxf(rm, fmaxf(sb[nb][e0], sb[nb][e1]));
            rm = fmaxf(rm, __shfl_xor_sync(0xffffffffu, rm, 1));
            rm = fmaxf(rm, __shfl_xor_sync(0xffffffffu, rm, 2));
            float mn = fmaxf(mi[hf], rm);
            cfac[hf] = exp2f(mi[hf] - mn);
            float rs = 0.f;
            #pragma unroll
            for (int nb = 0; nb < 8; nb++) {
                sb[nb][e0] = exp2f(sb[nb][e0] - mn);
                sb[nb][e1] = exp2f(sb[nb][e1] - mn);
                rs += sb[nb][e0] + sb[nb][e1];
            }
            rs += __shfl_xor_sync(0xffffffffu, rs, 1);
            rs += __shfl_xor_sync(0xffffffffu, rs, 2);
            li[hf] = li[hf] * cfac[hf] + rs;
            mi[hf] = mn;
            #pragma unroll
            for (int nbo = 0; nbo < 4; nbo++) {
                oacc[nbo][e0] *= cfac[hf];
                oacc[nbo][e1] *= cfac[hf];
            }
        }

        // ---- O += P @ V : relayout P (C-frag -> A-frag) via shuffles ----
        const int srcA = (lane & ~3) + (tq >> 1);
        const int srcB = srcA + 2;
        const bool odd = (tq & 1);
        #pragma unroll
        for (int kc = 0; kc < 8; kc++) {
            float vA0 = __shfl_sync(0xffffffffu, sb[kc][0], srcA);
            float vA1 = __shfl_sync(0xffffffffu, sb[kc][1], srcA);
            float vA2 = __shfl_sync(0xffffffffu, sb[kc][2], srcA);
            float vA3 = __shfl_sync(0xffffffffu, sb[kc][3], srcA);
            float vB0 = __shfl_sync(0xffffffffu, sb[kc][0], srcB);
            float vB1 = __shfl_sync(0xffffffffu, sb[kc][1], srcB);
            float vB2 = __shfl_sync(0xffffffffu, sb[kc][2], srcB);
            float vB3 = __shfl_sync(0xffffffffu, sb[kc][3], srcB);
            float pa0 = odd ? vA1 : vA0;   // (row g,   col kc*8+tq)
            float pa1 = odd ? vA3 : vA2;   // (row g+8, col kc*8+tq)
            float pa2 = odd ? vB1 : vB0;   // (row g,   col kc*8+tq+4)
            float pa3 = odd ? vB3 : vB2;   // (row g+8, col kc*8+tq+4)
            uint32_t phi[4], plo[4];
            tfsplit(pa0, phi[0], plo[0]);
            tfsplit(pa1, phi[1], plo[1]);
            tfsplit(pa2, phi[2], plo[2]);
            tfsplit(pa3, phi[3], plo[3]);
            #pragma unroll
            for (int nbo = 0; nbo < 4; nbo++) {
                float v0f = Vs[(kc * 8 + tq) * VS_STR + nbo * 8 + g];
                float v1f = Vs[(kc * 8 + tq + 4) * VS_STR + nbo * 8 + g];
                uint32_t v0h, v0l, v1h, v1l;
                tfsplit(v0f, v0h, v0l);
                tfsplit(v1f, v1h, v1l);
                mma_tf32(oacc[nbo], phi, v0h, v1h);
                mma_tf32(oacc[nbo], plo, v0h, v1h);
                mma_tf32(oacc[nbo], phi, v0l, v1l);
            }
        }
    }

    // ---- write O ----
    float inv0 = 1.f / li[0];
    float inv1 = 1.f / li[1];
    int r0 = q0 + w * 16 + g;
    #pragma unroll
    for (int nbo = 0; nbo < 4; nbo++) {
        int col = h * DH + nbo * 8 + tq * 2;
        *(float2*)&O[(size_t)r0 * HDIM + col] =
            make_float2(oacc[nbo][0] * inv0, oacc[nbo][1] * inv0);
        *(float2*)&O[(size_t)(r0 + 8) * HDIM + col] =
            make_float2(oacc[nbo][2] * inv1, oacc[nbo][3] * inv1);
    }
}

// ---------------- edge kernel: Hsum[dst] += relu(Atop[src] + Abot[dst]) ----
__global__ void edge_k(const float* __restrict__ At, const float* __restrict__ Ab,
                       const int* __restrict__ edges, float* __restrict__ Hsum,
                       float* __restrict__ deg, int E)
{
    const int lane   = threadIdx.x & 31;
    const int gw     = (blockIdx.x * blockDim.x + threadIdx.x) >> 5;
    const int nwarps = (gridDim.x * blockDim.x) >> 5;

    for (int e = gw; e < E; e += nwarps) {
        int src = edges[2 * e + 0];
        int dst = edges[2 * e + 1];
        const float4* ps = (const float4*)(At + (size_t)src * HDIM);
        const float4* pd = (const float4*)(Ab + (size_t)dst * HDIM);
        float* po = Hsum + (size_t)dst * HDIM;
        #pragma unroll
        for (int i = 0; i < 2; i++) {
            int idx = lane + 32 * i;
            float4 a = ps[idx], b = pd[idx];
            float4 r;
            r.x = fmaxf(a.x + b.x, 0.f);
            r.y = fmaxf(a.y + b.y, 0.f);
            r.z = fmaxf(a.z + b.z, 0.f);
            r.w = fmaxf(a.w + b.w, 0.f);
            asm volatile("red.global.add.v4.f32 [%0], {%1, %2, %3, %4};"
                         :: "l"(po + idx * 4), "f"(r.x), "f"(r.y), "f"(r.z), "f"(r.w)
                         : "memory");
        }
        if (lane == 0) atomicAdd(deg + dst, 1.f);
    }
}

// ---------------- launch ---------------------------------------------------
extern "C" void kernel_launch(void* const* d_in, const int* in_sizes, int n_in,
                              void* d_out, int out_size)
{
    const float* x    = (const float*)d_in[0];
    const int*   edges= (const int*)  d_in[1];
    const float* Wq   = (const float*)d_in[2];
    const float* Wk   = (const float*)d_in[3];
    const float* Wv   = (const float*)d_in[4];
    const float* bq   = (const float*)d_in[5];
    const float* bk   = (const float*)d_in[6];
    const float* bv   = (const float*)d_in[7];
    const float* Wo   = (const float*)d_in[8];
    const float* bo   = (const float*)d_in[9];
    const float* Wm1  = (const float*)d_in[10];
    const float* bm1  = (const float*)d_in[11];
    const float* Wm2  = (const float*)d_in[12];
    const float* bm2  = (const float*)d_in[13];
    const float* Wu1  = (const float*)d_in[14];
    const float* bu1  = (const float*)d_in[15];
    const float* Wu2  = (const float*)d_in[16];
    const float* bu2  = (const float*)d_in[17];
    float* out = (float*)d_out;

    const int N = in_sizes[0] / HDIM;   // 4096
    const int E = in_sizes[1] / 2;      // 131072

    float *Q, *K, *V, *attH, *att, *Atop, *Abot, *Hsum, *msg, *T1, *deg;
    cudaGetSymbolAddress((void**)&Q,    g_Q);
    cudaGetSymbolAddress((void**)&K,    g_K);
    cudaGetSymbolAddress((void**)&V,    g_V);
    cudaGetSymbolAddress((void**)&attH, g_attH);
    cudaGetSymbolAddress((void**)&att,  g_att);
    cudaGetSymbolAddress((void**)&Atop, g_Atop);
    cudaGetSymbolAddress((void**)&Abot, g_Abot);
    cudaGetSymbolAddress((void**)&Hsum, g_Hsum);
    cudaGetSymbolAddress((void**)&msg,  g_msg);
    cudaGetSymbolAddress((void**)&T1,   g_T1);
    cudaGetSymbolAddress((void**)&deg,  g_deg);

    dim3 gB(256);
    dim3 gG(HDIM / 64, N / 64);         // (4, 64)

    cudaMemsetAsync(Hsum, 0, (size_t)N * HDIM * sizeof(float));
    cudaMemsetAsync(deg,  0, (size_t)N * sizeof(float));

    // QKV projections
    gemm_k<false, true, false, false><<<gG, gB>>>(x, Wq, bq, nullptr, nullptr, Q, N, HDIM, HDIM);
    gemm_k<false, true, false, false><<<gG, gB>>>(x, Wk, bk, nullptr, nullptr, K, N, HDIM, HDIM);
    gemm_k<false, true, false, false><<<gG, gB>>>(x, Wv, bv, nullptr, nullptr, V, N, HDIM, HDIM);

    // attention (tensor cores)
    flash_mma<<<dim3(N / 128, NHEADS), 256>>>(Q, K, V, attH, N);

    // output projection
    gemm_k<false, true, false, false><<<gG, gB>>>(attH, Wo, bo, nullptr, nullptr, att, N, HDIM, HDIM);

    // edge MLP layer-1 factorization
    gemm_k<false, true,  false, false><<<gG, gB>>>(att, Wm1,             bm1, nullptr, nullptr, Atop, N, HDIM, HDIM);
    gemm_k<false, false, false, false><<<gG, gB>>>(att, Wm1 + HDIM*HDIM, nullptr, nullptr, nullptr, Abot, N, HDIM, HDIM);

    // per-edge relu + segment-sum of hidden
    edge_k<<<512, 256>>>(Atop, Abot, edges, Hsum, deg, E);

    // messages = Hsum @ Wm2 + deg * bm2
    gemm_k<false, true, false, true><<<gG, gB>>>(Hsum, Wm2, bm2, nullptr, deg, msg, N, HDIM, HDIM);

    // update MLP
    gemm_k<false, true, false, false><<<gG, gB>>>(att, Wu1,             bu1, nullptr, nullptr, T1, N, HDIM, HDIM);
    gemm_k<true,  false, true, false><<<gG, gB>>>(msg, Wu1 + HDIM*HDIM, nullptr, T1, nullptr, T1, N, HDIM, HDIM);

    // output
    gemm_k<false, true, false, false><<<gG, gB>>>(T1, Wu2, bu2, nullptr, nullptr, out, N, HDIM, HDIM);
}

// round 5
// speedup vs baseline: 1.9355x; 1.1371x over previous
#include <cuda_runtime.h>
#include <math.h>
#include <stdint.h>

#define HDIM 256
#define NHEADS 8
#define DH 32
#define NMAX 4096

// ---------------- scratch (static __device__ arrays: no allocations) -------
__device__ __align__(16) float g_Q   [NMAX * HDIM];
__device__ __align__(16) float g_K   [NMAX * HDIM];
__device__ __align__(16) float g_V   [NMAX * HDIM];
__device__ __align__(16) float g_attH[NMAX * HDIM];
__device__ __align__(16) float g_att [NMAX * HDIM];
__device__ __align__(16) float g_Atop[NMAX * HDIM];
__device__ __align__(16) float g_Abot[NMAX * HDIM];
__device__ __align__(16) float g_Hsum[NMAX * HDIM];
__device__ __align__(16) float g_msg [NMAX * HDIM];
__device__ __align__(16) float g_T1  [NMAX * HDIM];
__device__ __align__(16) float g_deg [NMAX];

// ---------------- SGEMM: C = act(A[M,K] @ W[K,N] + bias (+ Dadd)) ----------
template<bool RELU, bool BIAS, bool ADD, bool DEGB>
__global__ void gemm_k(const float* __restrict__ A, const float* __restrict__ W,
                       const float* __restrict__ bias, const float* __restrict__ Dadd,
                       const float* __restrict__ deg, float* __restrict__ C,
                       int M, int K, int N)
{
    __shared__ float As[16][68];   // [k][m], padded
    __shared__ float Bs[16][64];   // [k][n]

    const int t  = threadIdx.x;          // 0..255
    const int bm = blockIdx.y * 64;
    const int bn = blockIdx.x * 64;
    const int tr = t >> 4;               // 0..15 (row group)
    const int tc = t & 15;               // 0..15 (col group)

    const int ar = t >> 2;               // 0..63
    const int ac = (t & 3) << 2;         // 0,4,8,12
    const int br = t >> 4;               // 0..15
    const int bc = (t & 15) << 2;        // 0..60

    float acc[4][4];
    #pragma unroll
    for (int i = 0; i < 4; i++)
        #pragma unroll
        for (int j = 0; j < 4; j++) acc[i][j] = 0.f;

    for (int k0 = 0; k0 < K; k0 += 16) {
        float4 av = *(const float4*)&A[(size_t)(bm + ar) * K + k0 + ac];
        As[ac + 0][ar] = av.x;
        As[ac + 1][ar] = av.y;
        As[ac + 2][ar] = av.z;
        As[ac + 3][ar] = av.w;
        *(float4*)&Bs[br][bc] = *(const float4*)&W[(size_t)(k0 + br) * N + bn + bc];
        __syncthreads();

        #pragma unroll
        for (int k = 0; k < 16; k++) {
            float4 a4 = *(float4*)&As[k][tr << 2];
            float4 b4 = *(float4*)&Bs[k][tc << 2];
            float aa[4] = {a4.x, a4.y, a4.z, a4.w};
            float bb[4] = {b4.x, b4.y, b4.z, b4.w};
            #pragma unroll
            for (int i = 0; i < 4; i++)
                #pragma unroll
                for (int j = 0; j < 4; j++)
                    acc[i][j] = fmaf(aa[i], bb[j], acc[i][j]);
        }
        __syncthreads();
    }

    #pragma unroll
    for (int i = 0; i < 4; i++) {
        int row = bm + (tr << 2) + i;
        float dscale = DEGB ? deg[row] : 1.f;
        #pragma unroll
        for (int j = 0; j < 4; j++) {
            int col = bn + (tc << 2) + j;
            float v = acc[i][j];
            if (ADD)  v += Dadd[(size_t)row * N + col];
            if (BIAS) v += (DEGB ? dscale * bias[col] : bias[col]);
            if (RELU) v = fmaxf(v, 0.f);
            C[(size_t)row * N + col] = v;
        }
    }
}

// ---------------- tensor-core flash attention (3xTF32 mma.sync) -------------
// Block: 256 threads / 8 warps, 128 queries of one head; 64-key tiles.
// K and V are split into tf32 hi/lo COOPERATIVELY in smem at tile-load time
// (once per block-tile, not once per warp) — mma loops are pure LDS+MMA.
// P (produced in registers) goes C-frag -> A-frag via shuffles, split in regs.

__device__ __forceinline__ uint32_t f2tf(float x) {
    uint32_t r;
    asm("cvt.rna.tf32.f32 %0, %1;" : "=r"(r) : "f"(x));
    return r;
}
__device__ __forceinline__ void tfsplit(float x, uint32_t& hi, uint32_t& lo) {
    hi = f2tf(x);
    lo = f2tf(x - __uint_as_float(hi));
}
__device__ __forceinline__ void mma_tf32(float d[4], const uint32_t a[4],
                                         uint32_t b0, uint32_t b1) {
    asm volatile(
        "mma.sync.aligned.m16n8k8.row.col.f32.tf32.tf32.f32 "
        "{%0,%1,%2,%3}, {%4,%5,%6,%7}, {%8,%9}, {%0,%1,%2,%3};"
        : "+f"(d[0]), "+f"(d[1]), "+f"(d[2]), "+f"(d[3])
        : "r"(a[0]), "r"(a[1]), "r"(a[2]), "r"(a[3]), "r"(b0), "r"(b1));
}

#define KS_STR 36   // bank-conflict-free for K B-fragment pattern (g*36+tq)
#define VS_STR 40   // bank-conflict-free for V B-fragment pattern (tq*40+g)

__global__ void __launch_bounds__(256) flash_mma(
    const float* __restrict__ Qm, const float* __restrict__ Km,
    const float* __restrict__ Vm, float* __restrict__ O, int N)
{
    __shared__ uint32_t Khi[64 * KS_STR];
    __shared__ uint32_t Klo[64 * KS_STR];
    __shared__ uint32_t Vhi[64 * VS_STR];
    __shared__ uint32_t Vlo[64 * VS_STR];

    const int t    = threadIdx.x;
    const int w    = t >> 5;
    const int lane = t & 31;
    const int g    = lane >> 2;          // row within fragment
    const int tq   = lane & 3;           // thread in group
    const int h    = blockIdx.y;
    const int q0   = blockIdx.x * 128;
    const float sc = 1.44269504088896f / sqrtf((float)DH);

    // ---- stage Q tile (128 x 32) as raw floats into Khi/Vhi regions ----
    for (int i = t; i < 128 * 8; i += 256) {
        int row = i >> 3, c = (i & 7) << 2;
        float4 qv = *(const float4*)&Qm[(size_t)(q0 + row) * HDIM + h * DH + c];
        uint32_t* dst = (row < 64) ? &Khi[row * KS_STR + c]
                                   : &Vhi[(row - 64) * VS_STR + c];
        *(float4*)dst = qv;
    }
    __syncthreads();

    // ---- extract Q fragments (hi/lo), scaled; kept in regs all kernel ----
    uint32_t qhi[4][4], qlo[4][4];
    {
        int r0 = w * 16 + g;
        int r1 = r0 + 8;
        const float* p0 = (const float*)((r0 < 64) ? &Khi[r0 * KS_STR]
                                                   : &Vhi[(r0 - 64) * VS_STR]);
        const float* p1 = (const float*)((r1 < 64) ? &Khi[r1 * KS_STR]
                                                   : &Vhi[(r1 - 64) * VS_STR]);
        #pragma unroll
        for (int kc = 0; kc < 4; kc++) {
            int c0 = kc * 8 + tq, c1 = c0 + 4;
            tfsplit(p0[c0] * sc, qhi[kc][0], qlo[kc][0]);
            tfsplit(p1[c0] * sc, qhi[kc][1], qlo[kc][1]);
            tfsplit(p0[c1] * sc, qhi[kc][2], qlo[kc][2]);
            tfsplit(p1[c1] * sc, qhi[kc][3], qlo[kc][3]);
        }
    }

    float oacc[4][4];
    #pragma unroll
    for (int i = 0; i < 4; i++)
        #pragma unroll
        for (int j = 0; j < 4; j++) oacc[i][j] = 0.f;
    float mi[2] = {-1e30f, -1e30f};
    float li[2] = {0.f, 0.f};

    for (int kb = 0; kb < N; kb += 64) {
        __syncthreads();   // previous tile fully consumed (incl. Q staging)
        // cooperative load + tf32 hi/lo split of K and V tiles
        for (int i = t; i < 64 * 8; i += 256) {
            int n = i >> 3, c = (i & 7) << 2;
            size_t gidx = (size_t)(kb + n) * HDIM + h * DH + c;
            float4 kv = *(const float4*)&Km[gidx];
            float4 vv = *(const float4*)&Vm[gidx];
            uint32_t h0, l0, h1, l1, h2, l2, h3, l3;
            tfsplit(kv.x, h0, l0); tfsplit(kv.y, h1, l1);
            tfsplit(kv.z, h2, l2); tfsplit(kv.w, h3, l3);
            uint32_t* kh = &Khi[n * KS_STR + c];
            uint32_t* kl = &Klo[n * KS_STR + c];
            *(uint4*)kh = make_uint4(h0, h1, h2, h3);
            *(uint4*)kl = make_uint4(l0, l1, l2, l3);
            tfsplit(vv.x, h0, l0); tfsplit(vv.y, h1, l1);
            tfsplit(vv.z, h2, l2); tfsplit(vv.w, h3, l3);
            uint32_t* vh = &Vhi[n * VS_STR + c];
            uint32_t* vl = &Vlo[n * VS_STR + c];
            *(uint4*)vh = make_uint4(h0, h1, h2, h3);
            *(uint4*)vl = make_uint4(l0, l1, l2, l3);
        }
        __syncthreads();

        // ---- S = Q @ K^T : pure LDS + mma ----
        float sb[8][4];
        #pragma unroll
        for (int nb = 0; nb < 8; nb++)
            #pragma unroll
            for (int j = 0; j < 4; j++) sb[nb][j] = 0.f;

        #pragma unroll
        for (int kc = 0; kc < 4; kc++) {
            #pragma unroll
            for (int nb = 0; nb < 8; nb++) {
                int base = (nb * 8 + g) * KS_STR + kc * 8 + tq;
                uint32_t b0h = Khi[base], b1h = Khi[base + 4];
                uint32_t b0l = Klo[base], b1l = Klo[base + 4];
                mma_tf32(sb[nb], qhi[kc], b0h, b1h);
                mma_tf32(sb[nb], qlo[kc], b0h, b1h);
                mma_tf32(sb[nb], qhi[kc], b0l, b1l);
            }
        }

        // ---- online softmax on C fragments ----
        #pragma unroll
        for (int hf = 0; hf < 2; hf++) {
            int e0 = hf * 2, e1 = hf * 2 + 1;
            float rm = -1e30f;
            #pragma unroll
            for (int nb = 0; nb < 8; nb++)
                rm = fmaxf(rm, fmaxf(sb[nb][e0], sb[nb][e1]));
            rm = fmaxf(rm, __shfl_xor_sync(0xffffffffu, rm, 1));
            rm = fmaxf(rm, __shfl_xor_sync(0xffffffffu, rm, 2));
            float mn = fmaxf(mi[hf], rm);
            float c  = exp2f(mi[hf] - mn);
            float rs = 0.f;
            #pragma unroll
            for (int nb = 0; nb < 8; nb++) {
                sb[nb][e0] = exp2f(sb[nb][e0] - mn);
                sb[nb][e1] = exp2f(sb[nb][e1] - mn);
                rs += sb[nb][e0] + sb[nb][e1];
            }
            rs += __shfl_xor_sync(0xffffffffu, rs, 1);
            rs += __shfl_xor_sync(0xffffffffu, rs, 2);
            li[hf] = li[hf] * c + rs;
            mi[hf] = mn;
            #pragma unroll
            for (int nbo = 0; nbo < 4; nbo++) {
                oacc[nbo][e0] *= c;
                oacc[nbo][e1] *= c;
            }
        }

        // ---- O += P @ V : P relayout via shuffles, V hi/lo from smem ----
        const int srcA = (lane & ~3) + (tq >> 1);
        const int srcB = srcA + 2;
        const bool odd = (tq & 1);
        #pragma unroll
        for (int kc = 0; kc < 8; kc++) {
            float vA0 = __shfl_sync(0xffffffffu, sb[kc][0], srcA);
            float vA1 = __shfl_sync(0xffffffffu, sb[kc][1], srcA);
            float vA2 = __shfl_sync(0xffffffffu, sb[kc][2], srcA);
            float vA3 = __shfl_sync(0xffffffffu, sb[kc][3], srcA);
            float vB0 = __shfl_sync(0xffffffffu, sb[kc][0], srcB);
            float vB1 = __shfl_sync(0xffffffffu, sb[kc][1], srcB);
            float vB2 = __shfl_sync(0xffffffffu, sb[kc][2], srcB);
            float vB3 = __shfl_sync(0xffffffffu, sb[kc][3], srcB);
            float pa0 = odd ? vA1 : vA0;
            float pa1 = odd ? vA3 : vA2;
            float pa2 = odd ? vB1 : vB0;
            float pa3 = odd ? vB3 : vB2;
            uint32_t phi[4], plo[4];
            tfsplit(pa0, phi[0], plo[0]);
            tfsplit(pa1, phi[1], plo[1]);
            tfsplit(pa2, phi[2], plo[2]);
            tfsplit(pa3, phi[3], plo[3]);
            int b0 = (kc * 8 + tq) * VS_STR + g;
            int b1 = (kc * 8 + tq + 4) * VS_STR + g;
            #pragma unroll
            for (int nbo = 0; nbo < 4; nbo++) {
                uint32_t v0h = Vhi[b0 + nbo * 8], v1h = Vhi[b1 + nbo * 8];
                uint32_t v0l = Vlo[b0 + nbo * 8], v1l = Vlo[b1 + nbo * 8];
                mma_tf32(oacc[nbo], phi, v0h, v1h);
                mma_tf32(oacc[nbo], plo, v0h, v1h);
                mma_tf32(oacc[nbo], phi, v0l, v1l);
            }
        }
    }

    // ---- write O ----
    float inv0 = 1.f / li[0];
    float inv1 = 1.f / li[1];
    int r0 = q0 + w * 16 + g;
    #pragma unroll
    for (int nbo = 0; nbo < 4; nbo++) {
        int col = h * DH + nbo * 8 + tq * 2;
        *(float2*)&O[(size_t)r0 * HDIM + col] =
            make_float2(oacc[nbo][0] * inv0, oacc[nbo][1] * inv0);
        *(float2*)&O[(size_t)(r0 + 8) * HDIM + col] =
            make_float2(oacc[nbo][2] * inv1, oacc[nbo][3] * inv1);
    }
}

// ---------------- edge kernel: Hsum[dst] += relu(Atop[src] + Abot[dst]) ----
__global__ void edge_k(const float* __restrict__ At, const float* __restrict__ Ab,
                       const int* __restrict__ edges, float* __restrict__ Hsum,
                       float* __restrict__ deg, int E)
{
    const int lane   = threadIdx.x & 31;
    const int gw     = (blockIdx.x * blockDim.x + threadIdx.x) >> 5;
    const int nwarps = (gridDim.x * blockDim.x) >> 5;

    for (int e = gw; e < E; e += nwarps) {
        int src = edges[2 * e + 0];
        int dst = edges[2 * e + 1];
        const float4* ps = (const float4*)(At + (size_t)src * HDIM);
        const float4* pd = (const float4*)(Ab + (size_t)dst * HDIM);
        float* po = Hsum + (size_t)dst * HDIM;
        #pragma unroll
        for (int i = 0; i < 2; i++) {
            int idx = lane + 32 * i;
            float4 a = ps[idx], b = pd[idx];
            float4 r;
            r.x = fmaxf(a.x + b.x, 0.f);
            r.y = fmaxf(a.y + b.y, 0.f);
            r.z = fmaxf(a.z + b.z, 0.f);
            r.w = fmaxf(a.w + b.w, 0.f);
            asm volatile("red.global.add.v4.f32 [%0], {%1, %2, %3, %4};"
                         :: "l"(po + idx * 4), "f"(r.x), "f"(r.y), "f"(r.z), "f"(r.w)
                         : "memory");
        }
        if (lane == 0) atomicAdd(deg + dst, 1.f);
    }
}

// ---------------- launch ---------------------------------------------------
extern "C" void kernel_launch(void* const* d_in, const int* in_sizes, int n_in,
                              void* d_out, int out_size)
{
    const float* x    = (const float*)d_in[0];
    const int*   edges= (const int*)  d_in[1];
    const float* Wq   = (const float*)d_in[2];
    const float* Wk   = (const float*)d_in[3];
    const float* Wv   = (const float*)d_in[4];
    const float* bq   = (const float*)d_in[5];
    const float* bk   = (const float*)d_in[6];
    const float* bv   = (const float*)d_in[7];
    const float* Wo   = (const float*)d_in[8];
    const float* bo   = (const float*)d_in[9];
    const float* Wm1  = (const float*)d_in[10];
    const float* bm1  = (const float*)d_in[11];
    const float* Wm2  = (const float*)d_in[12];
    const float* bm2  = (const float*)d_in[13];
    const float* Wu1  = (const float*)d_in[14];
    const float* bu1  = (const float*)d_in[15];
    const float* Wu2  = (const float*)d_in[16];
    const float* bu2  = (const float*)d_in[17];
    float* out = (float*)d_out;

    const int N = in_sizes[0] / HDIM;   // 4096
    const int E = in_sizes[1] / 2;      // 131072

    float *Q, *K, *V, *attH, *att, *Atop, *Abot, *Hsum, *msg, *T1, *deg;
    cudaGetSymbolAddress((void**)&Q,    g_Q);
    cudaGetSymbolAddress((void**)&K,    g_K);
    cudaGetSymbolAddress((void**)&V,    g_V);
    cudaGetSymbolAddress((void**)&attH, g_attH);
    cudaGetSymbolAddress((void**)&att,  g_att);
    cudaGetSymbolAddress((void**)&Atop, g_Atop);
    cudaGetSymbolAddress((void**)&Abot, g_Abot);
    cudaGetSymbolAddress((void**)&Hsum, g_Hsum);
    cudaGetSymbolAddress((void**)&msg,  g_msg);
    cudaGetSymbolAddress((void**)&T1,   g_T1);
    cudaGetSymbolAddress((void**)&deg,  g_deg);

    dim3 gB(256);
    dim3 gG(HDIM / 64, N / 64);         // (4, 64)

    cudaMemsetAsync(Hsum, 0, (size_t)N * HDIM * sizeof(float));
    cudaMemsetAsync(deg,  0, (size_t)N * sizeof(float));

    // QKV projections
    gemm_k<false, true, false, false><<<gG, gB>>>(x, Wq, bq, nullptr, nullptr, Q, N, HDIM, HDIM);
    gemm_k<false, true, false, false><<<gG, gB>>>(x, Wk, bk, nullptr, nullptr, K, N, HDIM, HDIM);
    gemm_k<false, true, false, false><<<gG, gB>>>(x, Wv, bv, nullptr, nullptr, V, N, HDIM, HDIM);

    // attention (tensor cores)
    flash_mma<<<dim3(N / 128, NHEADS), 256>>>(Q, K, V, attH, N);

    // output projection
    gemm_k<false, true, false, false><<<gG, gB>>>(attH, Wo, bo, nullptr, nullptr, att, N, HDIM, HDIM);

    // edge MLP layer-1 factorization
    gemm_k<false, true,  false, false><<<gG, gB>>>(att, Wm1,             bm1, nullptr, nullptr, Atop, N, HDIM, HDIM);
    gemm_k<false, false, false, false><<<gG, gB>>>(att, Wm1 + HDIM*HDIM, nullptr, nullptr, nullptr, Abot, N, HDIM, HDIM);

    // per-edge relu + segment-sum of hidden
    edge_k<<<512, 256>>>(Atop, Abot, edges, Hsum, deg, E);

    // messages = Hsum @ Wm2 + deg * bm2
    gemm_k<false, true, false, true><<<gG, gB>>>(Hsum, Wm2, bm2, nullptr, deg, msg, N, HDIM, HDIM);

    // update MLP
    gemm_k<false, true, false, false><<<gG, gB>>>(att, Wu1,             bu1, nullptr, nullptr, T1, N, HDIM, HDIM);
    gemm_k<true,  false, true, false><<<gG, gB>>>(msg, Wu1 + HDIM*HDIM, nullptr, T1, nullptr, T1, N, HDIM, HDIM);

    // output
    gemm_k<false, true, false, false><<<gG, gB>>>(T1, Wu2, bu2, nullptr, nullptr, out, N, HDIM, HDIM);
}

// round 8
// speedup vs baseline: 2.1311x; 1.1010x over previous
#include <cuda_runtime.h>
#include <math.h>
#include <stdint.h>

#define HDIM 256
#define NHEADS 8
#define DH 32
#define NMAX 4096

// ---------------- scratch (static __device__ arrays: no allocations) -------
__device__ __align__(16) float g_Q   [NMAX * HDIM];
__device__ __align__(16) float g_K   [NMAX * HDIM];
__device__ __align__(16) float g_V   [NMAX * HDIM];
__device__ __align__(16) float g_attH[NMAX * HDIM];
__device__ __align__(16) float g_att [NMAX * HDIM];
__device__ __align__(16) float g_Atop[NMAX * HDIM];
__device__ __align__(16) float g_Abot[NMAX * HDIM];
__device__ __align__(16) float g_Hsum[NMAX * HDIM];
__device__ __align__(16) float g_msg [NMAX * HDIM];
__device__ __align__(16) float g_T1  [NMAX * HDIM];
__device__ __align__(16) float g_deg [NMAX];

// ---------------- tf32 helpers ---------------------------------------------
__device__ __forceinline__ uint32_t f2tf(float x) {
    uint32_t r;
    asm("cvt.rna.tf32.f32 %0, %1;" : "=r"(r) : "f"(x));
    return r;
}
__device__ __forceinline__ void tfsplit(float x, uint32_t& hi, uint32_t& lo) {
    hi = f2tf(x);
    lo = f2tf(x - __uint_as_float(hi));
}
__device__ __forceinline__ void mma_tf32(float d[4], const uint32_t a[4],
                                         uint32_t b0, uint32_t b1) {
    asm volatile(
        "mma.sync.aligned.m16n8k8.row.col.f32.tf32.tf32.f32 "
        "{%0,%1,%2,%3}, {%4,%5,%6,%7}, {%8,%9}, {%0,%1,%2,%3};"
        : "+f"(d[0]), "+f"(d[1]), "+f"(d[2]), "+f"(d[3])
        : "r"(a[0]), "r"(a[1]), "r"(a[2]), "r"(a[3]), "r"(b0), "r"(b1));
}

// ---------------- tensor-core GEMM (3xTF32): C = act(A@W + bias (+Dadd)) ----
// Block 64x64 output tile, 256 threads = 8 warps in 2(M)x4(N); warp = 32x16.
// K chunks of 32. A/W split to tf32 hi/lo cooperatively in smem.
// A stride 36 (banks g*4+tq, distinct); W [k][n] stride 72 (banks tq*8+g,
// distinct). Smem total 36.9 KB < 48 KB static; all indices bounds-audited:
//   A loader max word 63*36+24+7 = 2299 < 2304
//   W loader max word 31*72+56+7 = 2295 < 2304
//   A frag   max word (32+16+7)*36+24+7+4 -> 55*36+31 = 2011 < 2304
//   W frag   max word (31)*72+48+8+7      -> 2295     < 2304
#define AS_STR 36
#define WS_STR 72

template<bool RELU, bool BIAS, bool ADD, bool DEGB>
__global__ void __launch_bounds__(256) gemm_mma(
    const float* __restrict__ A, const float* __restrict__ W,
    const float* __restrict__ bias, const float* __restrict__ Dadd,
    const float* __restrict__ deg, float* __restrict__ C,
    int M, int K, int N)
{
    __shared__ uint32_t Ahi[64 * AS_STR];   //  9216 B
    __shared__ uint32_t Alo[64 * AS_STR];   //  9216 B
    __shared__ uint32_t Whi[32 * WS_STR];   //  9216 B
    __shared__ uint32_t Wlo[32 * WS_STR];   //  9216 B

    const int t    = threadIdx.x;
    const int w    = t >> 5;
    const int lane = t & 31;
    const int g    = lane >> 2;
    const int tq   = lane & 3;
    const int wm   = (w >> 2) * 32;      // warp row offset (0 or 32)
    const int wn   = (w & 3) * 16;       // warp col offset (0,16,32,48)
    const int bm   = blockIdx.y * 64;
    const int bn   = blockIdx.x * 64;

    float acc[2][2][4];                  // [mh][nb][cfrag]
    #pragma unroll
    for (int mh = 0; mh < 2; mh++)
        #pragma unroll
        for (int nb = 0; nb < 2; nb++)
            #pragma unroll
            for (int j = 0; j < 4; j++) acc[mh][nb][j] = 0.f;

    const int arow = t >> 2, akb = (t & 3) * 8;    // A: 64x32, 8 words/thread
    const int wkk  = t >> 3, wnb = (t & 7) * 8;    // W: 32x64, 8 words/thread

    for (int k0 = 0; k0 < K; k0 += 32) {
        __syncthreads();
        // A tile 64x32 -> hi/lo
        {
            const float* src = &A[(size_t)(bm + arow) * K + k0 + akb];
            #pragma unroll
            for (int j = 0; j < 8; j += 4) {
                float4 v = *(const float4*)(src + j);
                uint32_t h0,l0,h1,l1,h2,l2,h3,l3;
                tfsplit(v.x,h0,l0); tfsplit(v.y,h1,l1);
                tfsplit(v.z,h2,l2); tfsplit(v.w,h3,l3);
                *(uint4*)&Ahi[arow * AS_STR + akb + j] = make_uint4(h0,h1,h2,h3);
                *(uint4*)&Alo[arow * AS_STR + akb + j] = make_uint4(l0,l1,l2,l3);
            }
        }
        // W tile 32x64 -> hi/lo ([k][n], natural orientation)
        {
            const float* src = &W[(size_t)(k0 + wkk) * N + bn + wnb];
            #pragma unroll
            for (int j = 0; j < 8; j += 4) {
                float4 v = *(const float4*)(src + j);
                uint32_t h0,l0,h1,l1,h2,l2,h3,l3;
                tfsplit(v.x,h0,l0); tfsplit(v.y,h1,l1);
                tfsplit(v.z,h2,l2); tfsplit(v.w,h3,l3);
                *(uint4*)&Whi[wkk * WS_STR + wnb + j] = make_uint4(h0,h1,h2,h3);
                *(uint4*)&Wlo[wkk * WS_STR + wnb + j] = make_uint4(l0,l1,l2,l3);
            }
        }
        __syncthreads();

        #pragma unroll
        for (int kc = 0; kc < 4; kc++) {
            uint32_t bh[2][2], bl[2][2];
            #pragma unroll
            for (int nb = 0; nb < 2; nb++) {
                int i0 = (kc * 8 + tq) * WS_STR + wn + nb * 8 + g;
                int i1 = i0 + 4 * WS_STR;
                bh[nb][0] = Whi[i0]; bh[nb][1] = Whi[i1];
                bl[nb][0] = Wlo[i0]; bl[nb][1] = Wlo[i1];
            }
            #pragma unroll
            for (int mh = 0; mh < 2; mh++) {
                int r0 = (wm + mh * 16 + g) * AS_STR + kc * 8 + tq;
                int r1 = r0 + 8 * AS_STR;
                uint32_t ah[4] = {Ahi[r0], Ahi[r1], Ahi[r0 + 4], Ahi[r1 + 4]};
                uint32_t al[4] = {Alo[r0], Alo[r1], Alo[r0 + 4], Alo[r1 + 4]};
                #pragma unroll
                for (int nb = 0; nb < 2; nb++) {
                    mma_tf32(acc[mh][nb], ah, bh[nb][0], bh[nb][1]);
                    mma_tf32(acc[mh][nb], al, bh[nb][0], bh[nb][1]);
                    mma_tf32(acc[mh][nb], ah, bl[nb][0], bl[nb][1]);
                }
            }
        }
    }

    // epilogue: c-frag rows (g, g+8), cols tq*2, tq*2+1
    #pragma unroll
    for (int mh = 0; mh < 2; mh++) {
        int row0 = bm + wm + mh * 16 + g;
        int row1 = row0 + 8;
        float d0 = DEGB ? deg[row0] : 1.f;
        float d1 = DEGB ? deg[row1] : 1.f;
        #pragma unroll
        for (int nb = 0; nb < 2; nb++) {
            int col = bn + wn + nb * 8 + tq * 2;
            float v0 = acc[mh][nb][0], v1 = acc[mh][nb][1];
            float v2 = acc[mh][nb][2], v3 = acc[mh][nb][3];
            if (ADD) {
                float2 x0 = *(const float2*)&Dadd[(size_t)row0 * N + col];
                float2 x1 = *(const float2*)&Dadd[(size_t)row1 * N + col];
                v0 += x0.x; v1 += x0.y; v2 += x1.x; v3 += x1.y;
            }
            if (BIAS) {
                float b0 = bias[col], b1 = bias[col + 1];
                if (DEGB) { v0 += d0 * b0; v1 += d0 * b1; v2 += d1 * b0; v3 += d1 * b1; }
                else      { v0 += b0;      v1 += b1;      v2 += b0;      v3 += b1; }
            }
            if (RELU) {
                v0 = fmaxf(v0, 0.f); v1 = fmaxf(v1, 0.f);
                v2 = fmaxf(v2, 0.f); v3 = fmaxf(v3, 0.f);
            }
            *(float2*)&C[(size_t)row0 * N + col] = make_float2(v0, v1);
            *(float2*)&C[(size_t)row1 * N + col] = make_float2(v2, v3);
        }
    }
}

// ---------------- tensor-core flash attention (3xTF32 mma.sync) -------------
// (unchanged from round 5 — passed at 390us, rel_err 2.54e-5)
#define KS_STR 36
#define VS_STR 40

__global__ void __launch_bounds__(256) flash_mma(
    const float* __restrict__ Qm, const float* __restrict__ Km,
    const float* __restrict__ Vm, float* __restrict__ O, int N)
{
    __shared__ uint32_t Khi[64 * KS_STR];
    __shared__ uint32_t Klo[64 * KS_STR];
    __shared__ uint32_t Vhi[64 * VS_STR];
    __shared__ uint32_t Vlo[64 * VS_STR];

    const int t    = threadIdx.x;
    const int w    = t >> 5;
    const int lane = t & 31;
    const int g    = lane >> 2;
    const int tq   = lane & 3;
    const int h    = blockIdx.y;
    const int q0   = blockIdx.x * 128;
    const float sc = 1.44269504088896f / sqrtf((float)DH);

    for (int i = t; i < 128 * 8; i += 256) {
        int row = i >> 3, c = (i & 7) << 2;
        float4 qv = *(const float4*)&Qm[(size_t)(q0 + row) * HDIM + h * DH + c];
        uint32_t* dst = (row < 64) ? &Khi[row * KS_STR + c]
                                   : &Vhi[(row - 64) * VS_STR + c];
        *(float4*)dst = qv;
    }
    __syncthreads();

    uint32_t qhi[4][4], qlo[4][4];
    {
        int r0 = w * 16 + g;
        int r1 = r0 + 8;
        const float* p0 = (const float*)((r0 < 64) ? &Khi[r0 * KS_STR]
                                                   : &Vhi[(r0 - 64) * VS_STR]);
        const float* p1 = (const float*)((r1 < 64) ? &Khi[r1 * KS_STR]
                                                   : &Vhi[(r1 - 64) * VS_STR]);
        #pragma unroll
        for (int kc = 0; kc < 4; kc++) {
            int c0 = kc * 8 + tq, c1 = c0 + 4;
            tfsplit(p0[c0] * sc, qhi[kc][0], qlo[kc][0]);
            tfsplit(p1[c0] * sc, qhi[kc][1], qlo[kc][1]);
            tfsplit(p0[c1] * sc, qhi[kc][2], qlo[kc][2]);
            tfsplit(p1[c1] * sc, qhi[kc][3], qlo[kc][3]);
        }
    }

    float oacc[4][4];
    #pragma unroll
    for (int i = 0; i < 4; i++)
        #pragma unroll
        for (int j = 0; j < 4; j++) oacc[i][j] = 0.f;
    float mi[2] = {-1e30f, -1e30f};
    float li[2] = {0.f, 0.f};

    for (int kb = 0; kb < N; kb += 64) {
        __syncthreads();
        for (int i = t; i < 64 * 8; i += 256) {
            int n = i >> 3, c = (i & 7) << 2;
            size_t gidx = (size_t)(kb + n) * HDIM + h * DH + c;
            float4 kv = *(const float4*)&Km[gidx];
            float4 vv = *(const float4*)&Vm[gidx];
            uint32_t h0, l0, h1, l1, h2, l2, h3, l3;
            tfsplit(kv.x, h0, l0); tfsplit(kv.y, h1, l1);
            tfsplit(kv.z, h2, l2); tfsplit(kv.w, h3, l3);
            *(uint4*)&Khi[n * KS_STR + c] = make_uint4(h0, h1, h2, h3);
            *(uint4*)&Klo[n * KS_STR + c] = make_uint4(l0, l1, l2, l3);
            tfsplit(vv.x, h0, l0); tfsplit(vv.y, h1, l1);
            tfsplit(vv.z, h2, l2); tfsplit(vv.w, h3, l3);
            *(uint4*)&Vhi[n * VS_STR + c] = make_uint4(h0, h1, h2, h3);
            *(uint4*)&Vlo[n * VS_STR + c] = make_uint4(l0, l1, l2, l3);
        }
        __syncthreads();

        float sb[8][4];
        #pragma unroll
        for (int nb = 0; nb < 8; nb++)
            #pragma unroll
            for (int j = 0; j < 4; j++) sb[nb][j] = 0.f;

        #pragma unroll
        for (int kc = 0; kc < 4; kc++) {
            #pragma unroll
            for (int nb = 0; nb < 8; nb++) {
                int base = (nb * 8 + g) * KS_STR + kc * 8 + tq;
                uint32_t b0h = Khi[base], b1h = Khi[base + 4];
                uint32_t b0l = Klo[base], b1l = Klo[base + 4];
                mma_tf32(sb[nb], qhi[kc], b0h, b1h);
                mma_tf32(sb[nb], qlo[kc], b0h, b1h);
                mma_tf32(sb[nb], qhi[kc], b0l, b1l);
            }
        }

        #pragma unroll
        for (int hf = 0; hf < 2; hf++) {
            int e0 = hf * 2, e1 = hf * 2 + 1;
            float rm = -1e30f;
            #pragma unroll
            for (int nb = 0; nb < 8; nb++)
                rm = fmaxf(rm, fmaxf(sb[nb][e0], sb[nb][e1]));
            rm = fmaxf(rm, __shfl_xor_sync(0xffffffffu, rm, 1));
            rm = fmaxf(rm, __shfl_xor_sync(0xffffffffu, rm, 2));
            float mn = fmaxf(mi[hf], rm);
            float c  = exp2f(mi[hf] - mn);
            float rs = 0.f;
            #pragma unroll
            for (int nb = 0; nb < 8; nb++) {
                sb[nb][e0] = exp2f(sb[nb][e0] - mn);
                sb[nb][e1] = exp2f(sb[nb][e1] - mn);
                rs += sb[nb][e0] + sb[nb][e1];
            }
            rs += __shfl_xor_sync(0xffffffffu, rs, 1);
            rs += __shfl_xor_sync(0xffffffffu, rs, 2);
            li[hf] = li[hf] * c + rs;
            mi[hf] = mn;
            #pragma unroll
            for (int nbo = 0; nbo < 4; nbo++) {
                oacc[nbo][e0] *= c;
                oacc[nbo][e1] *= c;
            }
        }

        const int srcA = (lane & ~3) + (tq >> 1);
        const int srcB = srcA + 2;
        const bool odd = (tq & 1);
        #pragma unroll
        for (int kc = 0; kc < 8; kc++) {
            float vA0 = __shfl_sync(0xffffffffu, sb[kc][0], srcA);
            float vA1 = __shfl_sync(0xffffffffu, sb[kc][1], srcA);
            float vA2 = __shfl_sync(0xffffffffu, sb[kc][2], srcA);
            float vA3 = __shfl_sync(0xffffffffu, sb[kc][3], srcA);
            float vB0 = __shfl_sync(0xffffffffu, sb[kc][0], srcB);
            float vB1 = __shfl_sync(0xffffffffu, sb[kc][1], srcB);
            float vB2 = __shfl_sync(0xffffffffu, sb[kc][2], srcB);
            float vB3 = __shfl_sync(0xffffffffu, sb[kc][3], srcB);
            float pa0 = odd ? vA1 : vA0;
            float pa1 = odd ? vA3 : vA2;
            float pa2 = odd ? vB1 : vB0;
            float pa3 = odd ? vB3 : vB2;
            uint32_t phi[4], plo[4];
            tfsplit(pa0, phi[0], plo[0]);
            tfsplit(pa1, phi[1], plo[1]);
            tfsplit(pa2, phi[2], plo[2]);
            tfsplit(pa3, phi[3], plo[3]);
            int b0 = (kc * 8 + tq) * VS_STR + g;
            int b1 = (kc * 8 + tq + 4) * VS_STR + g;
            #pragma unroll
            for (int nbo = 0; nbo < 4; nbo++) {
                uint32_t v0h = Vhi[b0 + nbo * 8], v1h = Vhi[b1 + nbo * 8];
                uint32_t v0l = Vlo[b0 + nbo * 8], v1l = Vlo[b1 + nbo * 8];
                mma_tf32(oacc[nbo], phi, v0h, v1h);
                mma_tf32(oacc[nbo], plo, v0h, v1h);
                mma_tf32(oacc[nbo], phi, v0l, v1l);
            }
        }
    }

    float inv0 = 1.f / li[0];
    float inv1 = 1.f / li[1];
    int r0 = q0 + w * 16 + g;
    #pragma unroll
    for (int nbo = 0; nbo < 4; nbo++) {
        int col = h * DH + nbo * 8 + tq * 2;
        *(float2*)&O[(size_t)r0 * HDIM + col] =
            make_float2(oacc[nbo][0] * inv0, oacc[nbo][1] * inv0);
        *(float2*)&O[(size_t)(r0 + 8) * HDIM + col] =
            make_float2(oacc[nbo][2] * inv1, oacc[nbo][3] * inv1);
    }
}

// ---------------- edge kernel: Hsum[dst] += relu(Atop[src] + Abot[dst]) ----
__global__ void edge_k(const float* __restrict__ At, const float* __restrict__ Ab,
                       const int* __restrict__ edges, float* __restrict__ Hsum,
                       float* __restrict__ deg, int E)
{
    const int lane   = threadIdx.x & 31;
    const int gw     = (blockIdx.x * blockDim.x + threadIdx.x) >> 5;
    const int nwarps = (gridDim.x * blockDim.x) >> 5;

    for (int e = gw; e < E; e += nwarps) {
        int src = edges[2 * e + 0];
        int dst = edges[2 * e + 1];
        const float4* ps = (const float4*)(At + (size_t)src * HDIM);
        const float4* pd = (const float4*)(Ab + (size_t)dst * HDIM);
        float* po = Hsum + (size_t)dst * HDIM;
        #pragma unroll
        for (int i = 0; i < 2; i++) {
            int idx = lane + 32 * i;
            float4 a = ps[idx], b = pd[idx];
            float4 r;
            r.x = fmaxf(a.x + b.x, 0.f);
            r.y = fmaxf(a.y + b.y, 0.f);
            r.z = fmaxf(a.z + b.z, 0.f);
            r.w = fmaxf(a.w + b.w, 0.f);
            asm volatile("red.global.add.v4.f32 [%0], {%1, %2, %3, %4};"
                         :: "l"(po + idx * 4), "f"(r.x), "f"(r.y), "f"(r.z), "f"(r.w)
                         : "memory");
        }
        if (lane == 0) atomicAdd(deg + dst, 1.f);
    }
}

// ---------------- launch ---------------------------------------------------
extern "C" void kernel_launch(void* const* d_in, const int* in_sizes, int n_in,
                              void* d_out, int out_size)
{
    const float* x    = (const float*)d_in[0];
    const int*   edges= (const int*)  d_in[1];
    const float* Wq   = (const float*)d_in[2];
    const float* Wk   = (const float*)d_in[3];
    const float* Wv   = (const float*)d_in[4];
    const float* bq   = (const float*)d_in[5];
    const float* bk   = (const float*)d_in[6];
    const float* bv   = (const float*)d_in[7];
    const float* Wo   = (const float*)d_in[8];
    const float* bo   = (const float*)d_in[9];
    const float* Wm1  = (const float*)d_in[10];
    const float* bm1  = (const float*)d_in[11];
    const float* Wm2  = (const float*)d_in[12];
    const float* bm2  = (const float*)d_in[13];
    const float* Wu1  = (const float*)d_in[14];
    const float* bu1  = (const float*)d_in[15];
    const float* Wu2  = (const float*)d_in[16];
    const float* bu2  = (const float*)d_in[17];
    float* out = (float*)d_out;

    const int N = in_sizes[0] / HDIM;   // 4096
    const int E = in_sizes[1] / 2;      // 131072

    float *Q, *K, *V, *attH, *att, *Atop, *Abot, *Hsum, *msg, *T1, *deg;
    cudaGetSymbolAddress((void**)&Q,    g_Q);
    cudaGetSymbolAddress((void**)&K,    g_K);
    cudaGetSymbolAddress((void**)&V,    g_V);
    cudaGetSymbolAddress((void**)&attH, g_attH);
    cudaGetSymbolAddress((void**)&att,  g_att);
    cudaGetSymbolAddress((void**)&Atop, g_Atop);
    cudaGetSymbolAddress((void**)&Abot, g_Abot);
    cudaGetSymbolAddress((void**)&Hsum, g_Hsum);
    cudaGetSymbolAddress((void**)&msg,  g_msg);
    cudaGetSymbolAddress((void**)&T1,   g_T1);
    cudaGetSymbolAddress((void**)&deg,  g_deg);

    dim3 gB(256);
    dim3 gG(HDIM / 64, N / 64);         // (4, 64) = 256 blocks

    cudaMemsetAsync(Hsum, 0, (size_t)N * HDIM * sizeof(float));
    cudaMemsetAsync(deg,  0, (size_t)N * sizeof(float));

    // QKV projections
    gemm_mma<false, true, false, false><<<gG, gB>>>(x, Wq, bq, nullptr, nullptr, Q, N, HDIM, HDIM);
    gemm_mma<false, true, false, false><<<gG, gB>>>(x, Wk, bk, nullptr, nullptr, K, N, HDIM, HDIM);
    gemm_mma<false, true, false, false><<<gG, gB>>>(x, Wv, bv, nullptr, nullptr, V, N, HDIM, HDIM);

    // attention (tensor cores)
    flash_mma<<<dim3(N / 128, NHEADS), 256>>>(Q, K, V, attH, N);

    // output projection
    gemm_mma<false, true, false, false><<<gG, gB>>>(attH, Wo, bo, nullptr, nullptr, att, N, HDIM, HDIM);

    // edge MLP layer-1 factorization
    gemm_mma<false, true,  false, false><<<gG, gB>>>(att, Wm1,             bm1, nullptr, nullptr, Atop, N, HDIM, HDIM);
    gemm_mma<false, false, false, false><<<gG, gB>>>(att, Wm1 + HDIM*HDIM, nullptr, nullptr, nullptr, Abot, N, HDIM, HDIM);

    // per-edge relu + segment-sum of hidden
    edge_k<<<512, 256>>>(Atop, Abot, edges, Hsum, deg, E);

    // messages = Hsum @ Wm2 + deg * bm2
    gemm_mma<false, true, false, true><<<gG, gB>>>(Hsum, Wm2, bm2, nullptr, deg, msg, N, HDIM, HDIM);

    // update MLP
    gemm_mma<false, true, false, false><<<gG, gB>>>(att, Wu1,             bu1, nullptr, nullptr, T1, N, HDIM, HDIM);
    gemm_mma<true,  false, true, false><<<gG, gB>>>(msg, Wu1 + HDIM*HDIM, nullptr, T1, nullptr, T1, N, HDIM, HDIM);

    // output
    gemm_mma<false, true, false, false><<<gG, gB>>>(T1, Wu2, bu2, nullptr, nullptr, out, N, HDIM, HDIM);
}

// round 9
// speedup vs baseline: 2.5595x; 1.2010x over previous
#include <cuda_runtime.h>
#include <math.h>
#include <stdint.h>

#define HDIM 256
#define NHEADS 8
#define DH 32
#define NMAX 4096

// ---------------- scratch (static __device__ arrays: no allocations) -------
__device__ __align__(16) float g_Q   [NMAX * HDIM];
__device__ __align__(16) float g_K   [NMAX * HDIM];
__device__ __align__(16) float g_V   [NMAX * HDIM];
__device__ __align__(16) float g_attH[NMAX * HDIM];
__device__ __align__(16) float g_att [NMAX * HDIM];
__device__ __align__(16) float g_Atop[NMAX * HDIM];
__device__ __align__(16) float g_Abot[NMAX * HDIM];
__device__ __align__(16) float g_Hsum[NMAX * HDIM];
__device__ __align__(16) float g_msg [NMAX * HDIM];
__device__ __align__(16) float g_T1  [NMAX * HDIM];
__device__ __align__(16) float g_deg [NMAX];

// ---------------- tf32 helpers ---------------------------------------------
__device__ __forceinline__ uint32_t f2tf(float x) {
    uint32_t r;
    asm("cvt.rna.tf32.f32 %0, %1;" : "=r"(r) : "f"(x));
    return r;
}
__device__ __forceinline__ void tfsplit(float x, uint32_t& hi, uint32_t& lo) {
    hi = f2tf(x);
    lo = f2tf(x - __uint_as_float(hi));
}
__device__ __forceinline__ void mma_tf32(float d[4], const uint32_t a[4],
                                         uint32_t b0, uint32_t b1) {
    asm volatile(
        "mma.sync.aligned.m16n8k8.row.col.f32.tf32.tf32.f32 "
        "{%0,%1,%2,%3}, {%4,%5,%6,%7}, {%8,%9}, {%0,%1,%2,%3};"
        : "+f"(d[0]), "+f"(d[1]), "+f"(d[2]), "+f"(d[3])
        : "r"(a[0]), "r"(a[1]), "r"(a[2]), "r"(a[3]), "r"(b0), "r"(b1));
}

// ---------------- tensor-core GEMM (3xTF32): C = act(A@W + bias (+Dadd)) ----
// (unchanged from round 8 — passing)
#define AS_STR 36
#define WS_STR 72

template<bool RELU, bool BIAS, bool ADD, bool DEGB>
__global__ void __launch_bounds__(256) gemm_mma(
    const float* __restrict__ A, const float* __restrict__ W,
    const float* __restrict__ bias, const float* __restrict__ Dadd,
    const float* __restrict__ deg, float* __restrict__ C,
    int M, int K, int N)
{
    __shared__ uint32_t Ahi[64 * AS_STR];
    __shared__ uint32_t Alo[64 * AS_STR];
    __shared__ uint32_t Whi[32 * WS_STR];
    __shared__ uint32_t Wlo[32 * WS_STR];

    const int t    = threadIdx.x;
    const int w    = t >> 5;
    const int lane = t & 31;
    const int g    = lane >> 2;
    const int tq   = lane & 3;
    const int wm   = (w >> 2) * 32;
    const int wn   = (w & 3) * 16;
    const int bm   = blockIdx.y * 64;
    const int bn   = blockIdx.x * 64;

    float acc[2][2][4];
    #pragma unroll
    for (int mh = 0; mh < 2; mh++)
        #pragma unroll
        for (int nb = 0; nb < 2; nb++)
            #pragma unroll
            for (int j = 0; j < 4; j++) acc[mh][nb][j] = 0.f;

    const int arow = t >> 2, akb = (t & 3) * 8;
    const int wkk  = t >> 3, wnb = (t & 7) * 8;

    for (int k0 = 0; k0 < K; k0 += 32) {
        __syncthreads();
        {
            const float* src = &A[(size_t)(bm + arow) * K + k0 + akb];
            #pragma unroll
            for (int j = 0; j < 8; j += 4) {
                float4 v = *(const float4*)(src + j);
                uint32_t h0,l0,h1,l1,h2,l2,h3,l3;
                tfsplit(v.x,h0,l0); tfsplit(v.y,h1,l1);
                tfsplit(v.z,h2,l2); tfsplit(v.w,h3,l3);
                *(uint4*)&Ahi[arow * AS_STR + akb + j] = make_uint4(h0,h1,h2,h3);
                *(uint4*)&Alo[arow * AS_STR + akb + j] = make_uint4(l0,l1,l2,l3);
            }
        }
        {
            const float* src = &W[(size_t)(k0 + wkk) * N + bn + wnb];
            #pragma unroll
            for (int j = 0; j < 8; j += 4) {
                float4 v = *(const float4*)(src + j);
                uint32_t h0,l0,h1,l1,h2,l2,h3,l3;
                tfsplit(v.x,h0,l0); tfsplit(v.y,h1,l1);
                tfsplit(v.z,h2,l2); tfsplit(v.w,h3,l3);
                *(uint4*)&Whi[wkk * WS_STR + wnb + j] = make_uint4(h0,h1,h2,h3);
                *(uint4*)&Wlo[wkk * WS_STR + wnb + j] = make_uint4(l0,l1,l2,l3);
            }
        }
        __syncthreads();

        #pragma unroll
        for (int kc = 0; kc < 4; kc++) {
            uint32_t bh[2][2], bl[2][2];
            #pragma unroll
            for (int nb = 0; nb < 2; nb++) {
                int i0 = (kc * 8 + tq) * WS_STR + wn + nb * 8 + g;
                int i1 = i0 + 4 * WS_STR;
                bh[nb][0] = Whi[i0]; bh[nb][1] = Whi[i1];
                bl[nb][0] = Wlo[i0]; bl[nb][1] = Wlo[i1];
            }
            #pragma unroll
            for (int mh = 0; mh < 2; mh++) {
                int r0 = (wm + mh * 16 + g) * AS_STR + kc * 8 + tq;
                int r1 = r0 + 8 * AS_STR;
                uint32_t ah[4] = {Ahi[r0], Ahi[r1], Ahi[r0 + 4], Ahi[r1 + 4]};
                uint32_t al[4] = {Alo[r0], Alo[r1], Alo[r0 + 4], Alo[r1 + 4]};
                #pragma unroll
                for (int nb = 0; nb < 2; nb++) {
                    mma_tf32(acc[mh][nb], ah, bh[nb][0], bh[nb][1]);
                    mma_tf32(acc[mh][nb], al, bh[nb][0], bh[nb][1]);
                    mma_tf32(acc[mh][nb], ah, bl[nb][0], bl[nb][1]);
                }
            }
        }
    }

    #pragma unroll
    for (int mh = 0; mh < 2; mh++) {
        int row0 = bm + wm + mh * 16 + g;
        int row1 = row0 + 8;
        float d0 = DEGB ? deg[row0] : 1.f;
        float d1 = DEGB ? deg[row1] : 1.f;
        #pragma unroll
        for (int nb = 0; nb < 2; nb++) {
            int col = bn + wn + nb * 8 + tq * 2;
            float v0 = acc[mh][nb][0], v1 = acc[mh][nb][1];
            float v2 = acc[mh][nb][2], v3 = acc[mh][nb][3];
            if (ADD) {
                float2 x0 = *(const float2*)&Dadd[(size_t)row0 * N + col];
                float2 x1 = *(const float2*)&Dadd[(size_t)row1 * N + col];
                v0 += x0.x; v1 += x0.y; v2 += x1.x; v3 += x1.y;
            }
            if (BIAS) {
                float b0 = bias[col], b1 = bias[col + 1];
                if (DEGB) { v0 += d0 * b0; v1 += d0 * b1; v2 += d1 * b0; v3 += d1 * b1; }
                else      { v0 += b0;      v1 += b1;      v2 += b0;      v3 += b1; }
            }
            if (RELU) {
                v0 = fmaxf(v0, 0.f); v1 = fmaxf(v1, 0.f);
                v2 = fmaxf(v2, 0.f); v3 = fmaxf(v3, 0.f);
            }
            *(float2*)&C[(size_t)row0 * N + col] = make_float2(v0, v1);
            *(float2*)&C[(size_t)row1 * N + col] = make_float2(v2, v3);
        }
    }
}

// ---------------- tensor-core flash attention (2xTF32 mma.sync) -------------
// K and V are truncated to plain tf32 in smem (hi only); the hi/lo split is
// kept only on the register operands Q and P. Per logical mma: 2 HW mmas
// (ah.bh + al.bh). Neglected a.b_lo term ~1.4e-4 relative — inside budget.
// Halves K/V smem footprint (19.5 KB), read volume, and loader ALU.
#define KS_STR 36
#define VS_STR 40

__global__ void __launch_bounds__(256) flash_mma(
    const float* __restrict__ Qm, const float* __restrict__ Km,
    const float* __restrict__ Vm, float* __restrict__ O, int N)
{
    __shared__ uint32_t Khi[64 * KS_STR];
    __shared__ uint32_t Vhi[64 * VS_STR];

    const int t    = threadIdx.x;
    const int w    = t >> 5;
    const int lane = t & 31;
    const int g    = lane >> 2;
    const int tq   = lane & 3;
    const int h    = blockIdx.y;
    const int q0   = blockIdx.x * 128;
    const float sc = 1.44269504088896f / sqrtf((float)DH);

    // ---- stage Q tile (128 x 32) as raw floats into Khi/Vhi regions ----
    for (int i = t; i < 128 * 8; i += 256) {
        int row = i >> 3, c = (i & 7) << 2;
        float4 qv = *(const float4*)&Qm[(size_t)(q0 + row) * HDIM + h * DH + c];
        uint32_t* dst = (row < 64) ? &Khi[row * KS_STR + c]
                                   : &Vhi[(row - 64) * VS_STR + c];
        *(float4*)dst = qv;
    }
    __syncthreads();

    // ---- Q fragments (hi/lo), scaled; registers for whole kernel ----
    uint32_t qhi[4][4], qlo[4][4];
    {
        int r0 = w * 16 + g;
        int r1 = r0 + 8;
        const float* p0 = (const float*)((r0 < 64) ? &Khi[r0 * KS_STR]
                                                   : &Vhi[(r0 - 64) * VS_STR]);
        const float* p1 = (const float*)((r1 < 64) ? &Khi[r1 * KS_STR]
                                                   : &Vhi[(r1 - 64) * VS_STR]);
        #pragma unroll
        for (int kc = 0; kc < 4; kc++) {
            int c0 = kc * 8 + tq, c1 = c0 + 4;
            tfsplit(p0[c0] * sc, qhi[kc][0], qlo[kc][0]);
            tfsplit(p1[c0] * sc, qhi[kc][1], qlo[kc][1]);
            tfsplit(p0[c1] * sc, qhi[kc][2], qlo[kc][2]);
            tfsplit(p1[c1] * sc, qhi[kc][3], qlo[kc][3]);
        }
    }

    float oacc[4][4];
    #pragma unroll
    for (int i = 0; i < 4; i++)
        #pragma unroll
        for (int j = 0; j < 4; j++) oacc[i][j] = 0.f;
    float mi[2] = {-1e30f, -1e30f};
    float li[2] = {0.f, 0.f};

    for (int kb = 0; kb < N; kb += 64) {
        __syncthreads();
        // K/V tiles: plain tf32 truncation, hi only
        for (int i = t; i < 64 * 8; i += 256) {
            int n = i >> 3, c = (i & 7) << 2;
            size_t gidx = (size_t)(kb + n) * HDIM + h * DH + c;
            float4 kv = *(const float4*)&Km[gidx];
            float4 vv = *(const float4*)&Vm[gidx];
            *(uint4*)&Khi[n * KS_STR + c] =
                make_uint4(f2tf(kv.x), f2tf(kv.y), f2tf(kv.z), f2tf(kv.w));
            *(uint4*)&Vhi[n * VS_STR + c] =
                make_uint4(f2tf(vv.x), f2tf(vv.y), f2tf(vv.z), f2tf(vv.w));
        }
        __syncthreads();

        // ---- S = Q @ K^T : 2xTF32 ----
        float sb[8][4];
        #pragma unroll
        for (int nb = 0; nb < 8; nb++)
            #pragma unroll
            for (int j = 0; j < 4; j++) sb[nb][j] = 0.f;

        #pragma unroll
        for (int kc = 0; kc < 4; kc++) {
            #pragma unroll
            for (int nb = 0; nb < 8; nb++) {
                int base = (nb * 8 + g) * KS_STR + kc * 8 + tq;
                uint32_t b0h = Khi[base], b1h = Khi[base + 4];
                mma_tf32(sb[nb], qhi[kc], b0h, b1h);
                mma_tf32(sb[nb], qlo[kc], b0h, b1h);
            }
        }

        // ---- online softmax on C fragments ----
        #pragma unroll
        for (int hf = 0; hf < 2; hf++) {
            int e0 = hf * 2, e1 = hf * 2 + 1;
            float rm = -1e30f;
            #pragma unroll
            for (int nb = 0; nb < 8; nb++)
                rm = fmaxf(rm, fmaxf(sb[nb][e0], sb[nb][e1]));
            rm = fmaxf(rm, __shfl_xor_sync(0xffffffffu, rm, 1));
            rm = fmaxf(rm, __shfl_xor_sync(0xffffffffu, rm, 2));
            float mn = fmaxf(mi[hf], rm);
            float c  = exp2f(mi[hf] - mn);
            float rs = 0.f;
            #pragma unroll
            for (int nb = 0; nb < 8; nb++) {
                sb[nb][e0] = exp2f(sb[nb][e0] - mn);
                sb[nb][e1] = exp2f(sb[nb][e1] - mn);
                rs += sb[nb][e0] + sb[nb][e1];
            }
            rs += __shfl_xor_sync(0xffffffffu, rs, 1);
            rs += __shfl_xor_sync(0xffffffffu, rs, 2);
            li[hf] = li[hf] * c + rs;
            mi[hf] = mn;
            #pragma unroll
            for (int nbo = 0; nbo < 4; nbo++) {
                oacc[nbo][e0] *= c;
                oacc[nbo][e1] *= c;
            }
        }

        // ---- O += P @ V : P hi/lo in regs, V tf32 from smem (2xTF32) ----
        const int srcA = (lane & ~3) + (tq >> 1);
        const int srcB = srcA + 2;
        const bool odd = (tq & 1);
        #pragma unroll
        for (int kc = 0; kc < 8; kc++) {
            float vA0 = __shfl_sync(0xffffffffu, sb[kc][0], srcA);
            float vA1 = __shfl_sync(0xffffffffu, sb[kc][1], srcA);
            float vA2 = __shfl_sync(0xffffffffu, sb[kc][2], srcA);
            float vA3 = __shfl_sync(0xffffffffu, sb[kc][3], srcA);
            float vB0 = __shfl_sync(0xffffffffu, sb[kc][0], srcB);
            float vB1 = __shfl_sync(0xffffffffu, sb[kc][1], srcB);
            float vB2 = __shfl_sync(0xffffffffu, sb[kc][2], srcB);
            float vB3 = __shfl_sync(0xffffffffu, sb[kc][3], srcB);
            float pa0 = odd ? vA1 : vA0;
            float pa1 = odd ? vA3 : vA2;
            float pa2 = odd ? vB1 : vB0;
            float pa3 = odd ? vB3 : vB2;
            uint32_t phi[4], plo[4];
            tfsplit(pa0, phi[0], plo[0]);
            tfsplit(pa1, phi[1], plo[1]);
            tfsplit(pa2, phi[2], plo[2]);
            tfsplit(pa3, phi[3], plo[3]);
            int b0 = (kc * 8 + tq) * VS_STR + g;
            int b1 = (kc * 8 + tq + 4) * VS_STR + g;
            #pragma unroll
            for (int nbo = 0; nbo < 4; nbo++) {
                uint32_t v0h = Vhi[b0 + nbo * 8], v1h = Vhi[b1 + nbo * 8];
                mma_tf32(oacc[nbo], phi, v0h, v1h);
                mma_tf32(oacc[nbo], plo, v0h, v1h);
            }
        }
    }

    float inv0 = 1.f / li[0];
    float inv1 = 1.f / li[1];
    int r0 = q0 + w * 16 + g;
    #pragma unroll
    for (int nbo = 0; nbo < 4; nbo++) {
        int col = h * DH + nbo * 8 + tq * 2;
        *(float2*)&O[(size_t)r0 * HDIM + col] =
            make_float2(oacc[nbo][0] * inv0, oacc[nbo][1] * inv0);
        *(float2*)&O[(size_t)(r0 + 8) * HDIM + col] =
            make_float2(oacc[nbo][2] * inv1, oacc[nbo][3] * inv1);
    }
}

// ---------------- edge kernel: Hsum[dst] += relu(Atop[src] + Abot[dst]) ----
__global__ void edge_k(const float* __restrict__ At, const float* __restrict__ Ab,
                       const int* __restrict__ edges, float* __restrict__ Hsum,
                       float* __restrict__ deg, int E)
{
    const int lane   = threadIdx.x & 31;
    const int gw     = (blockIdx.x * blockDim.x + threadIdx.x) >> 5;
    const int nwarps = (gridDim.x * blockDim.x) >> 5;

    for (int e = gw; e < E; e += nwarps) {
        int src = edges[2 * e + 0];
        int dst = edges[2 * e + 1];
        const float4* ps = (const float4*)(At + (size_t)src * HDIM);
        const float4* pd = (const float4*)(Ab + (size_t)dst * HDIM);
        float* po = Hsum + (size_t)dst * HDIM;
        #pragma unroll
        for (int i = 0; i < 2; i++) {
            int idx = lane + 32 * i;
            float4 a = ps[idx], b = pd[idx];
            float4 r;
            r.x = fmaxf(a.x + b.x, 0.f);
            r.y = fmaxf(a.y + b.y, 0.f);
            r.z = fmaxf(a.z + b.z, 0.f);
            r.w = fmaxf(a.w + b.w, 0.f);
            asm volatile("red.global.add.v4.f32 [%0], {%1, %2, %3, %4};"
                         :: "l"(po + idx * 4), "f"(r.x), "f"(r.y), "f"(r.z), "f"(r.w)
                         : "memory");
        }
        if (lane == 0) atomicAdd(deg + dst, 1.f);
    }
}

// ---------------- launch ---------------------------------------------------
extern "C" void kernel_launch(void* const* d_in, const int* in_sizes, int n_in,
                              void* d_out, int out_size)
{
    const float* x    = (const float*)d_in[0];
    const int*   edges= (const int*)  d_in[1];
    const float* Wq   = (const float*)d_in[2];
    const float* Wk   = (const float*)d_in[3];
    const float* Wv   = (const float*)d_in[4];
    const float* bq   = (const float*)d_in[5];
    const float* bk   = (const float*)d_in[6];
    const float* bv   = (const float*)d_in[7];
    const float* Wo   = (const float*)d_in[8];
    const float* bo   = (const float*)d_in[9];
    const float* Wm1  = (const float*)d_in[10];
    const float* bm1  = (const float*)d_in[11];
    const float* Wm2  = (const float*)d_in[12];
    const float* bm2  = (const float*)d_in[13];
    const float* Wu1  = (const float*)d_in[14];
    const float* bu1  = (const float*)d_in[15];
    const float* Wu2  = (const float*)d_in[16];
    const float* bu2  = (const float*)d_in[17];
    float* out = (float*)d_out;

    const int N = in_sizes[0] / HDIM;   // 4096
    const int E = in_sizes[1] / 2;      // 131072

    float *Q, *K, *V, *attH, *att, *Atop, *Abot, *Hsum, *msg, *T1, *deg;
    cudaGetSymbolAddress((void**)&Q,    g_Q);
    cudaGetSymbolAddress((void**)&K,    g_K);
    cudaGetSymbolAddress((void**)&V,    g_V);
    cudaGetSymbolAddress((void**)&attH, g_attH);
    cudaGetSymbolAddress((void**)&att,  g_att);
    cudaGetSymbolAddress((void**)&Atop, g_Atop);
    cudaGetSymbolAddress((void**)&Abot, g_Abot);
    cudaGetSymbolAddress((void**)&Hsum, g_Hsum);
    cudaGetSymbolAddress((void**)&msg,  g_msg);
    cudaGetSymbolAddress((void**)&T1,   g_T1);
    cudaGetSymbolAddress((void**)&deg,  g_deg);

    dim3 gB(256);
    dim3 gG(HDIM / 64, N / 64);         // (4, 64) = 256 blocks

    cudaMemsetAsync(Hsum, 0, (size_t)N * HDIM * sizeof(float));
    cudaMemsetAsync(deg,  0, (size_t)N * sizeof(float));

    // QKV projections
    gemm_mma<false, true, false, false><<<gG, gB>>>(x, Wq, bq, nullptr, nullptr, Q, N, HDIM, HDIM);
    gemm_mma<false, true, false, false><<<gG, gB>>>(x, Wk, bk, nullptr, nullptr, K, N, HDIM, HDIM);
    gemm_mma<false, true, false, false><<<gG, gB>>>(x, Wv, bv, nullptr, nullptr, V, N, HDIM, HDIM);

    // attention (tensor cores, 2xTF32)
    flash_mma<<<dim3(N / 128, NHEADS), 256>>>(Q, K, V, attH, N);

    // output projection
    gemm_mma<false, true, false, false><<<gG, gB>>>(attH, Wo, bo, nullptr, nullptr, att, N, HDIM, HDIM);

    // edge MLP layer-1 factorization
    gemm_mma<false, true,  false, false><<<gG, gB>>>(att, Wm1,             bm1, nullptr, nullptr, Atop, N, HDIM, HDIM);
    gemm_mma<false, false, false, false><<<gG, gB>>>(att, Wm1 + HDIM*HDIM, nullptr, nullptr, nullptr, Abot, N, HDIM, HDIM);

    // per-edge relu + segment-sum of hidden
    edge_k<<<512, 256>>>(Atop, Abot, edges, Hsum, deg, E);

    // messages = Hsum @ Wm2 + deg * bm2
    gemm_mma<false, true, false, true><<<gG, gB>>>(Hsum, Wm2, bm2, nullptr, deg, msg, N, HDIM, HDIM);

    // update MLP
    gemm_mma<false, true, false, false><<<gG, gB>>>(att, Wu1,             bu1, nullptr, nullptr, T1, N, HDIM, HDIM);
    gemm_mma<true,  false, true, false><<<gG, gB>>>(msg, Wu1 + HDIM*HDIM, nullptr, T1, nullptr, T1, N, HDIM, HDIM);

    // output
    gemm_mma<false, true, false, false><<<gG, gB>>>(T1, Wu2, bu2, nullptr, nullptr, out, N, HDIM, HDIM);
}

// round 11
// speedup vs baseline: 2.6513x; 1.0359x over previous
#include <cuda_runtime.h>
#include <math.h>
#include <stdint.h>

#define HDIM 256
#define NHEADS 8
#define DH 32
#define NMAX 4096

// ---------------- scratch (static __device__ arrays: no allocations) -------
__device__ __align__(16) float g_Q   [NMAX * HDIM];
__device__ __align__(16) float g_K   [NMAX * HDIM];
__device__ __align__(16) float g_V   [NMAX * HDIM];
__device__ __align__(16) float g_attH[NMAX * HDIM];
__device__ __align__(16) float g_att [NMAX * HDIM];
__device__ __align__(16) float g_Atop[NMAX * HDIM];
__device__ __align__(16) float g_Abot[NMAX * HDIM];
__device__ __align__(16) float g_Hsum[NMAX * HDIM];
__device__ __align__(16) float g_msg [NMAX * HDIM];
__device__ __align__(16) float g_T1  [NMAX * HDIM];
__device__ __align__(16) float g_deg [NMAX];

// ---------------- tf32 helpers ---------------------------------------------
__device__ __forceinline__ uint32_t f2tf(float x) {
    uint32_t r;
    asm("cvt.rna.tf32.f32 %0, %1;" : "=r"(r) : "f"(x));
    return r;
}
__device__ __forceinline__ void tfsplit(float x, uint32_t& hi, uint32_t& lo) {
    hi = f2tf(x);
    lo = f2tf(x - __uint_as_float(hi));
}
__device__ __forceinline__ void mma_tf32(float d[4], const uint32_t a[4],
                                         uint32_t b0, uint32_t b1) {
    asm volatile(
        "mma.sync.aligned.m16n8k8.row.col.f32.tf32.tf32.f32 "
        "{%0,%1,%2,%3}, {%4,%5,%6,%7}, {%8,%9}, {%0,%1,%2,%3};"
        : "+f"(d[0]), "+f"(d[1]), "+f"(d[2]), "+f"(d[3])
        : "r"(a[0]), "r"(a[1]), "r"(a[2]), "r"(a[3]), "r"(b0), "r"(b1));
}
__device__ __forceinline__ void cpa16(void* smem, const void* g) {
    uint32_t s = (uint32_t)__cvta_generic_to_shared(smem);
    asm volatile("cp.async.cg.shared.global [%0], [%1], 16;"
                 :: "r"(s), "l"(g) : "memory");
}

// ---------------- tensor-core GEMM (3xTF32): C = act(A@W + bias (+Dadd)) ----
// (unchanged from round 8/9 — passing)
#define AS_STR 36
#define WS_STR 72

template<bool RELU, bool BIAS, bool ADD, bool DEGB>
__global__ void __launch_bounds__(256) gemm_mma(
    const float* __restrict__ A, const float* __restrict__ W,
    const float* __restrict__ bias, const float* __restrict__ Dadd,
    const float* __restrict__ deg, float* __restrict__ C,
    int M, int K, int N)
{
    __shared__ uint32_t Ahi[64 * AS_STR];
    __shared__ uint32_t Alo[64 * AS_STR];
    __shared__ uint32_t Whi[32 * WS_STR];
    __shared__ uint32_t Wlo[32 * WS_STR];

    const int t    = threadIdx.x;
    const int w    = t >> 5;
    const int lane = t & 31;
    const int g    = lane >> 2;
    const int tq   = lane & 3;
    const int wm   = (w >> 2) * 32;
    const int wn   = (w & 3) * 16;
    const int bm   = blockIdx.y * 64;
    const int bn   = blockIdx.x * 64;

    float acc[2][2][4];
    #pragma unroll
    for (int mh = 0; mh < 2; mh++)
        #pragma unroll
        for (int nb = 0; nb < 2; nb++)
            #pragma unroll
            for (int j = 0; j < 4; j++) acc[mh][nb][j] = 0.f;

    const int arow = t >> 2, akb = (t & 3) * 8;
    const int wkk  = t >> 3, wnb = (t & 7) * 8;

    for (int k0 = 0; k0 < K; k0 += 32) {
        __syncthreads();
        {
            const float* src = &A[(size_t)(bm + arow) * K + k0 + akb];
            #pragma unroll
            for (int j = 0; j < 8; j += 4) {
                float4 v = *(const float4*)(src + j);
                uint32_t h0,l0,h1,l1,h2,l2,h3,l3;
                tfsplit(v.x,h0,l0); tfsplit(v.y,h1,l1);
                tfsplit(v.z,h2,l2); tfsplit(v.w,h3,l3);
                *(uint4*)&Ahi[arow * AS_STR + akb + j] = make_uint4(h0,h1,h2,h3);
                *(uint4*)&Alo[arow * AS_STR + akb + j] = make_uint4(l0,l1,l2,l3);
            }
        }
        {
            const float* src = &W[(size_t)(k0 + wkk) * N + bn + wnb];
            #pragma unroll
            for (int j = 0; j < 8; j += 4) {
                float4 v = *(const float4*)(src + j);
                uint32_t h0,l0,h1,l1,h2,l2,h3,l3;
                tfsplit(v.x,h0,l0); tfsplit(v.y,h1,l1);
                tfsplit(v.z,h2,l2); tfsplit(v.w,h3,l3);
                *(uint4*)&Whi[wkk * WS_STR + wnb + j] = make_uint4(h0,h1,h2,h3);
                *(uint4*)&Wlo[wkk * WS_STR + wnb + j] = make_uint4(l0,l1,l2,l3);
            }
        }
        __syncthreads();

        #pragma unroll
        for (int kc = 0; kc < 4; kc++) {
            uint32_t bh[2][2], bl[2][2];
            #pragma unroll
            for (int nb = 0; nb < 2; nb++) {
                int i0 = (kc * 8 + tq) * WS_STR + wn + nb * 8 + g;
                int i1 = i0 + 4 * WS_STR;
                bh[nb][0] = Whi[i0]; bh[nb][1] = Whi[i1];
                bl[nb][0] = Wlo[i0]; bl[nb][1] = Wlo[i1];
            }
            #pragma unroll
            for (int mh = 0; mh < 2; mh++) {
                int r0 = (wm + mh * 16 + g) * AS_STR + kc * 8 + tq;
                int r1 = r0 + 8 * AS_STR;
                uint32_t ah[4] = {Ahi[r0], Ahi[r1], Ahi[r0 + 4], Ahi[r1 + 4]};
                uint32_t al[4] = {Alo[r0], Alo[r1], Alo[r0 + 4], Alo[r1 + 4]};
                #pragma unroll
                for (int nb = 0; nb < 2; nb++) {
                    mma_tf32(acc[mh][nb], ah, bh[nb][0], bh[nb][1]);
                    mma_tf32(acc[mh][nb], al, bh[nb][0], bh[nb][1]);
                    mma_tf32(acc[mh][nb], ah, bl[nb][0], bl[nb][1]);
                }
            }
        }
    }

    #pragma unroll
    for (int mh = 0; mh < 2; mh++) {
        int row0 = bm + wm + mh * 16 + g;
        int row1 = row0 + 8;
        float d0 = DEGB ? deg[row0] : 1.f;
        float d1 = DEGB ? deg[row1] : 1.f;
        #pragma unroll
        for (int nb = 0; nb < 2; nb++) {
            int col = bn + wn + nb * 8 + tq * 2;
            float v0 = acc[mh][nb][0], v1 = acc[mh][nb][1];
            float v2 = acc[mh][nb][2], v3 = acc[mh][nb][3];
            if (ADD) {
                float2 x0 = *(const float2*)&Dadd[(size_t)row0 * N + col];
                float2 x1 = *(const float2*)&Dadd[(size_t)row1 * N + col];
                v0 += x0.x; v1 += x0.y; v2 += x1.x; v3 += x1.y;
            }
            if (BIAS) {
                float b0 = bias[col], b1 = bias[col + 1];
                if (DEGB) { v0 += d0 * b0; v1 += d0 * b1; v2 += d1 * b0; v3 += d1 * b1; }
                else      { v0 += b0;      v1 += b1;      v2 += b0;      v3 += b1; }
            }
            if (RELU) {
                v0 = fmaxf(v0, 0.f); v1 = fmaxf(v1, 0.f);
                v2 = fmaxf(v2, 0.f); v3 = fmaxf(v3, 0.f);
            }
            *(float2*)&C[(size_t)row0 * N + col] = make_float2(v0, v1);
            *(float2*)&C[(size_t)row1 * N + col] = make_float2(v2, v3);
        }
    }
}

// ---------------- flash attention: cp.async double-buffer + 2xTF32 ----------
// K/V stored as RAW fp32 in smem via cp.async (HW truncates mma operands to
// tf32 — no cvt in the loader at all). Double-buffered tiles: tile i+1's
// cp.async is in flight during tile i's mma phase. Q/P stay rna hi/lo split
// in registers (2 mmas per logical mma).
#define KS_STR 36
#define VS_STR 40

__global__ void __launch_bounds__(256) flash_mma(
    const float* __restrict__ Qm, const float* __restrict__ Km,
    const float* __restrict__ Vm, float* __restrict__ O, int N)
{
    __shared__ uint32_t Khi[2][64 * KS_STR];   // 18.4 KB
    __shared__ uint32_t Vhi[2][64 * VS_STR];   // 20.5 KB

    const int t    = threadIdx.x;
    const int w    = t >> 5;
    const int lane = t & 31;
    const int g    = lane >> 2;
    const int tq   = lane & 3;
    const int h    = blockIdx.y;
    const int q0   = blockIdx.x * 128;
    const float sc = 1.44269504088896f / sqrtf((float)DH);

    // ---- stage Q tile (128 x 32) raw into buffer-0 regions ----
    for (int i = t; i < 128 * 8; i += 256) {
        int row = i >> 3, c = (i & 7) << 2;
        float4 qv = *(const float4*)&Qm[(size_t)(q0 + row) * HDIM + h * DH + c];
        uint32_t* dst = (row < 64) ? &Khi[0][row * KS_STR + c]
                                   : &Vhi[0][(row - 64) * VS_STR + c];
        *(float4*)dst = qv;
    }
    __syncthreads();

    // ---- Q fragments (rna hi/lo), scaled; registers for whole kernel ----
    uint32_t qhi[4][4], qlo[4][4];
    {
        int r0 = w * 16 + g;
        int r1 = r0 + 8;
        const float* p0 = (const float*)((r0 < 64) ? &Khi[0][r0 * KS_STR]
                                                   : &Vhi[0][(r0 - 64) * VS_STR]);
        const float* p1 = (const float*)((r1 < 64) ? &Khi[0][r1 * KS_STR]
                                                   : &Vhi[0][(r1 - 64) * VS_STR]);
        #pragma unroll
        for (int kc = 0; kc < 4; kc++) {
            int c0 = kc * 8 + tq, c1 = c0 + 4;
            tfsplit(p0[c0] * sc, qhi[kc][0], qlo[kc][0]);
            tfsplit(p1[c0] * sc, qhi[kc][1], qlo[kc][1]);
            tfsplit(p0[c1] * sc, qhi[kc][2], qlo[kc][2]);
            tfsplit(p1[c1] * sc, qhi[kc][3], qlo[kc][3]);
        }
    }
    __syncthreads();   // all warps done reading Q staging before tile-0 load

    // ---- prefetch tile 0 into buffer 0 (raw fp32, pure copy) ----
    for (int i = t; i < 64 * 8; i += 256) {
        int n = i >> 3, c = (i & 7) << 2;
        size_t gidx = (size_t)n * HDIM + h * DH + c;
        cpa16(&Khi[0][n * KS_STR + c], &Km[gidx]);
        cpa16(&Vhi[0][n * VS_STR + c], &Vm[gidx]);
    }
    asm volatile("cp.async.commit_group;" ::: "memory");

    float oacc[4][4];
    #pragma unroll
    for (int i = 0; i < 4; i++)
        #pragma unroll
        for (int j = 0; j < 4; j++) oacc[i][j] = 0.f;
    float mi[2] = {-1e30f, -1e30f};
    float li[2] = {0.f, 0.f};

    const int ntiles = N >> 6;
    for (int it = 0; it < ntiles; it++) {
        const int p = it & 1;

        // prefetch next tile into the other buffer (its readers finished at
        // the trailing __syncthreads of the previous iteration)
        if (it + 1 < ntiles) {
            int kb1 = (it + 1) << 6;
            for (int i = t; i < 64 * 8; i += 256) {
                int n = i >> 3, c = (i & 7) << 2;
                size_t gidx = (size_t)(kb1 + n) * HDIM + h * DH + c;
                cpa16(&Khi[1 - p][n * KS_STR + c], &Km[gidx]);
                cpa16(&Vhi[1 - p][n * VS_STR + c], &Vm[gidx]);
            }
            asm volatile("cp.async.commit_group;" ::: "memory");
            asm volatile("cp.async.wait_group 1;" ::: "memory");
        } else {
            asm volatile("cp.async.wait_group 0;" ::: "memory");
        }
        __syncthreads();   // tile `it` visible to all warps

        // ---- S = Q @ K^T : 2xTF32 (K raw fp32, HW-truncated) ----
        float sb[8][4];
        #pragma unroll
        for (int nb = 0; nb < 8; nb++)
            #pragma unroll
            for (int j = 0; j < 4; j++) sb[nb][j] = 0.f;

        #pragma unroll
        for (int kc = 0; kc < 4; kc++) {
            #pragma unroll
            for (int nb = 0; nb < 8; nb++) {
                int base = (nb * 8 + g) * KS_STR + kc * 8 + tq;
                uint32_t b0h = Khi[p][base], b1h = Khi[p][base + 4];
                mma_tf32(sb[nb], qhi[kc], b0h, b1h);
                mma_tf32(sb[nb], qlo[kc], b0h, b1h);
            }
        }

        // ---- online softmax on C fragments ----
        #pragma unroll
        for (int hf = 0; hf < 2; hf++) {
            int e0 = hf * 2, e1 = hf * 2 + 1;
            float rm = -1e30f;
            #pragma unroll
            for (int nb = 0; nb < 8; nb++)
                rm = fmaxf(rm, fmaxf(sb[nb][e0], sb[nb][e1]));
            rm = fmaxf(rm, __shfl_xor_sync(0xffffffffu, rm, 1));
            rm = fmaxf(rm, __shfl_xor_sync(0xffffffffu, rm, 2));
            float mn = fmaxf(mi[hf], rm);
            float c  = exp2f(mi[hf] - mn);
            float rs = 0.f;
            #pragma unroll
            for (int nb = 0; nb < 8; nb++) {
                sb[nb][e0] = exp2f(sb[nb][e0] - mn);
                sb[nb][e1] = exp2f(sb[nb][e1] - mn);
                rs += sb[nb][e0] + sb[nb][e1];
            }
            rs += __shfl_xor_sync(0xffffffffu, rs, 1);
            rs += __shfl_xor_sync(0xffffffffu, rs, 2);
            li[hf] = li[hf] * c + rs;
            mi[hf] = mn;
            #pragma unroll
            for (int nbo = 0; nbo < 4; nbo++) {
                oacc[nbo][e0] *= c;
                oacc[nbo][e1] *= c;
            }
        }

        // ---- O += P @ V : P rna hi/lo in regs, V raw fp32 (2xTF32) ----
        const int srcA = (lane & ~3) + (tq >> 1);
        const int srcB = srcA + 2;
        const bool odd = (tq & 1);
        #pragma unroll
        for (int kc = 0; kc < 8; kc++) {
            float vA0 = __shfl_sync(0xffffffffu, sb[kc][0], srcA);
            float vA1 = __shfl_sync(0xffffffffu, sb[kc][1], srcA);
            float vA2 = __shfl_sync(0xffffffffu, sb[kc][2], srcA);
            float vA3 = __shfl_sync(0xffffffffu, sb[kc][3], srcA);
            float vB0 = __shfl_sync(0xffffffffu, sb[kc][0], srcB);
            float vB1 = __shfl_sync(0xffffffffu, sb[kc][1], srcB);
            float vB2 = __shfl_sync(0xffffffffu, sb[kc][2], srcB);
            float vB3 = __shfl_sync(0xffffffffu, sb[kc][3], srcB);
            float pa0 = odd ? vA1 : vA0;
            float pa1 = odd ? vA3 : vA2;
            float pa2 = odd ? vB1 : vB0;
            float pa3 = odd ? vB3 : vB2;
            uint32_t phi[4], plo[4];
            tfsplit(pa0, phi[0], plo[0]);
            tfsplit(pa1, phi[1], plo[1]);
            tfsplit(pa2, phi[2], plo[2]);
            tfsplit(pa3, phi[3], plo[3]);
            int b0 = (kc * 8 + tq) * VS_STR + g;
            int b1 = (kc * 8 + tq + 4) * VS_STR + g;
            #pragma unroll
            for (int nbo = 0; nbo < 4; nbo++) {
                uint32_t v0h = Vhi[p][b0 + nbo * 8], v1h = Vhi[p][b1 + nbo * 8];
                mma_tf32(oacc[nbo], phi, v0h, v1h);
                mma_tf32(oacc[nbo], plo, v0h, v1h);
            }
        }
        __syncthreads();   // tile `it` fully consumed; next prefetch may write
    }

    float inv0 = 1.f / li[0];
    float inv1 = 1.f / li[1];
    int r0 = q0 + w * 16 + g;
    #pragma unroll
    for (int nbo = 0; nbo < 4; nbo++) {
        int col = h * DH + nbo * 8 + tq * 2;
        *(float2*)&O[(size_t)r0 * HDIM + col] =
            make_float2(oacc[nbo][0] * inv0, oacc[nbo][1] * inv0);
        *(float2*)&O[(size_t)(r0 + 8) * HDIM + col] =
            make_float2(oacc[nbo][2] * inv1, oacc[nbo][3] * inv1);
    }
}

// ---------------- edge kernel: Hsum[dst] += relu(Atop[src] + Abot[dst]) ----
__global__ void edge_k(const float* __restrict__ At, const float* __restrict__ Ab,
                       const int* __restrict__ edges, float* __restrict__ Hsum,
                       float* __restrict__ deg, int E)
{
    const int lane   = threadIdx.x & 31;
    const int gw     = (blockIdx.x * blockDim.x + threadIdx.x) >> 5;
    const int nwarps = (gridDim.x * blockDim.x) >> 5;

    for (int e = gw; e < E; e += nwarps) {
        int src = edges[2 * e + 0];
        int dst = edges[2 * e + 1];
        const float4* ps = (const float4*)(At + (size_t)src * HDIM);
        const float4* pd = (const float4*)(Ab + (size_t)dst * HDIM);
        float* po = Hsum + (size_t)dst * HDIM;
        #pragma unroll
        for (int i = 0; i < 2; i++) {
            int idx = lane + 32 * i;
            float4 a = ps[idx], b = pd[idx];
            float4 r;
            r.x = fmaxf(a.x + b.x, 0.f);
            r.y = fmaxf(a.y + b.y, 0.f);
            r.z = fmaxf(a.z + b.z, 0.f);
            r.w = fmaxf(a.w + b.w, 0.f);
            asm volatile("red.global.add.v4.f32 [%0], {%1, %2, %3, %4};"
                         :: "l"(po + idx * 4), "f"(r.x), "f"(r.y), "f"(r.z), "f"(r.w)
                         : "memory");
        }
        if (lane == 0) atomicAdd(deg + dst, 1.f);
    }
}

// ---------------- launch ---------------------------------------------------
extern "C" void kernel_launch(void* const* d_in, const int* in_sizes, int n_in,
                              void* d_out, int out_size)
{
    const float* x    = (const float*)d_in[0];
    const int*   edges= (const int*)  d_in[1];
    const float* Wq   = (const float*)d_in[2];
    const float* Wk   = (const float*)d_in[3];
    const float* Wv   = (const float*)d_in[4];
    const float* bq   = (const float*)d_in[5];
    const float* bk   = (const float*)d_in[6];
    const float* bv   = (const float*)d_in[7];
    const float* Wo   = (const float*)d_in[8];
    const float* bo   = (const float*)d_in[9];
    const float* Wm1  = (const float*)d_in[10];
    const float* bm1  = (const float*)d_in[11];
    const float* Wm2  = (const float*)d_in[12];
    const float* bm2  = (const float*)d_in[13];
    const float* Wu1  = (const float*)d_in[14];
    const float* bu1  = (const float*)d_in[15];
    const float* Wu2  = (const float*)d_in[16];
    const float* bu2  = (const float*)d_in[17];
    float* out = (float*)d_out;

    const int N = in_sizes[0] / HDIM;   // 4096
    const int E = in_sizes[1] / 2;      // 131072

    float *Q, *K, *V, *attH, *att, *Atop, *Abot, *Hsum, *msg, *T1, *deg;
    cudaGetSymbolAddress((void**)&Q,    g_Q);
    cudaGetSymbolAddress((void**)&K,    g_K);
    cudaGetSymbolAddress((void**)&V,    g_V);
    cudaGetSymbolAddress((void**)&attH, g_attH);
    cudaGetSymbolAddress((void**)&att,  g_att);
    cudaGetSymbolAddress((void**)&Atop, g_Atop);
    cudaGetSymbolAddress((void**)&Abot, g_Abot);
    cudaGetSymbolAddress((void**)&Hsum, g_Hsum);
    cudaGetSymbolAddress((void**)&msg,  g_msg);
    cudaGetSymbolAddress((void**)&T1,   g_T1);
    cudaGetSymbolAddress((void**)&deg,  g_deg);

    dim3 gB(256);
    dim3 gG(HDIM / 64, N / 64);         // (4, 64) = 256 blocks

    cudaMemsetAsync(Hsum, 0, (size_t)N * HDIM * sizeof(float));
    cudaMemsetAsync(deg,  0, (size_t)N * sizeof(float));

    // QKV projections
    gemm_mma<false, true, false, false><<<gG, gB>>>(x, Wq, bq, nullptr, nullptr, Q, N, HDIM, HDIM);
    gemm_mma<false, true, false, false><<<gG, gB>>>(x, Wk, bk, nullptr, nullptr, K, N, HDIM, HDIM);
    gemm_mma<false, true, false, false><<<gG, gB>>>(x, Wv, bv, nullptr, nullptr, V, N, HDIM, HDIM);

    // attention (tensor cores, cp.async double-buffered 2xTF32)
    flash_mma<<<dim3(N / 128, NHEADS), 256>>>(Q, K, V, attH, N);

    // output projection
    gemm_mma<false, true, false, false><<<gG, gB>>>(attH, Wo, bo, nullptr, nullptr, att, N, HDIM, HDIM);

    // edge MLP layer-1 factorization
    gemm_mma<false, true,  false, false><<<gG, gB>>>(att, Wm1,             bm1, nullptr, nullptr, Atop, N, HDIM, HDIM);
    gemm_mma<false, false, false, false><<<gG, gB>>>(att, Wm1 + HDIM*HDIM, nullptr, nullptr, nullptr, Abot, N, HDIM, HDIM);

    // per-edge relu + segment-sum of hidden
    edge_k<<<512, 256>>>(Atop, Abot, edges, Hsum, deg, E);

    // messages = Hsum @ Wm2 + deg * bm2
    gemm_mma<false, true, false, true><<<gG, gB>>>(Hsum, Wm2, bm2, nullptr, deg, msg, N, HDIM, HDIM);

    // update MLP
    gemm_mma<false, true, false, false><<<gG, gB>>>(att, Wu1,             bu1, nullptr, nullptr, T1, N, HDIM, HDIM);
    gemm_mma<true,  false, true, false><<<gG, gB>>>(msg, Wu1 + HDIM*HDIM, nullptr, T1, nullptr, T1, N, HDIM, HDIM);

    // output
    gemm_mma<false, true, false, false><<<gG, gB>>>(T1, Wu2, bu2, nullptr, nullptr, out, N, HDIM, HDIM);
}